// round 1
// baseline (speedup 1.0000x reference)
#include <cuda_runtime.h>
#include <cstddef>

// ---------------------------------------------------------------------------
// SpikingTransformerBlock  (B=4, C=512, T=4, N=512, L=2048, HID=2048, H=8, d=64)
//
// Pipeline:
//   xq  = LIF_T(BN_attn(x))                                  [B,C,L] spikes
//   sq  = LIF_T(BN_q(q_w @ xq)); sk, sv likewise
//   M   = k^T v  per (b,h)   (64x64 exact integer counts)
//   so  = spike( (q @ M) * 0.125 / 1.5 - 1 )                 [B,C,L]
//   x1  = x + proj_w @ so + proj_b
//   s   = LIF_T(BN_mlp(x1))
//   s2  = LIF_T(BN_fc1(fc1_w @ s + fc1_b))                   [B,HID,L]
//   out = x1 + fc2_w @ s2 + fc2_b
// ---------------------------------------------------------------------------

#define BB 4
#define CC 512
#define TT 4
#define NN 512
#define LL 2048
#define HID 2048
#define NH 8
#define HD 64

// -------------------- device scratch (no malloc allowed) -------------------
__device__ float g_xq[(size_t)BB * CC * LL];        // 16 MB (input spikes; reused for MLP spikes)
__device__ float g_y [(size_t)BB * HID * LL];       // 64 MB (pre-LIF gemm out, reused)
__device__ float g_sq[(size_t)BB * CC * LL];
__device__ float g_sk[(size_t)BB * CC * LL];
__device__ float g_sv[(size_t)BB * CC * LL];
__device__ float g_M [(size_t)BB * NH * HD * HD];
__device__ float g_so[(size_t)BB * CC * LL];
__device__ float g_x1[(size_t)BB * CC * LL];
__device__ float g_s2[(size_t)BB * HID * LL];       // 64 MB
__device__ float g_scale[6 * 2048];
__device__ float g_shift[6 * 2048];

// -------------------- BN param folding -------------------------------------
// p = [gamma, beta, mean, var] each [Cdim].  out = acc*scale + shift, where
// shift folds an optional conv bias applied BEFORE the BN.
__global__ void bnprep_k(const float* __restrict__ p, const float* __restrict__ bias,
                         float* __restrict__ scale, float* __restrict__ shift, int Cdim) {
    int c = blockIdx.x * blockDim.x + threadIdx.x;
    if (c >= Cdim) return;
    float g  = p[c];
    float be = p[Cdim + c];
    float m  = p[2 * Cdim + c];
    float va = p[3 * Cdim + c];
    float inv = g / sqrtf(va + 1e-5f);
    float sh  = be - m * inv;
    if (bias) sh += bias[c] * inv;
    scale[c] = inv;
    shift[c] = sh;
}

// -------------------- BN + multistep LIF over T ----------------------------
// x layout [B, Cdim, L] with l = t*N + n.  LIF recurrence is over t for fixed (b,c,n).
__global__ void lif_bn_k(const float* __restrict__ x, float* __restrict__ s,
                         const float* __restrict__ scale, const float* __restrict__ shift) {
    int idx = blockIdx.x * blockDim.x + threadIdx.x;   // over B*C*N = 1,048,576
    int n = idx & (NN - 1);
    int c = (idx >> 9) & (CC - 1);
    int b = idx >> 18;
    size_t base = (((size_t)b * CC + c) * LL) + n;
    float sc = scale[c], sh = shift[c];
    float v = 0.f;
#pragma unroll
    for (int t = 0; t < TT; ++t) {
        float xv = x[base + (size_t)t * NN] * sc + sh;
        v += (xv - v) / 1.5f;
        float sp = (v >= 1.0f) ? 1.f : 0.f;
        s[base + (size_t)t * NN] = sp;
        v = (v >= 1.0f) ? 0.f : v;
    }
}

// -------------------- multistep LIF over T (no BN) -------------------------
__global__ void lif_t_k(const float* __restrict__ y, float* __restrict__ s, int Cdim) {
    int idx = blockIdx.x * blockDim.x + threadIdx.x;   // over B*Cdim*N
    int n = idx & (NN - 1);
    int rest = idx >> 9;
    int c = rest % Cdim;
    int b = rest / Cdim;
    size_t base = (((size_t)b * Cdim + c) * LL) + n;
    float v = 0.f;
#pragma unroll
    for (int t = 0; t < TT; ++t) {
        float xv = y[base + (size_t)t * NN];
        v += (xv - v) / 1.5f;
        float sp = (v >= 1.0f) ? 1.f : 0.f;
        s[base + (size_t)t * NN] = sp;
        v = (v >= 1.0f) ? 0.f : v;
    }
}

// -------------------- batched SGEMM + epilogue ------------------------------
// out[b] = W[Co,Ci] @ S[b][Ci,L], then per-row  *scale[co] + shift[co] (+ resid).
// 128x128 tile, K-tile 8, 256 threads, 8x8 per thread.  All dims divide tiles.
__global__ void __launch_bounds__(256) gemm_bn_k(
    const float* __restrict__ W, const float* __restrict__ S,
    float* __restrict__ out,
    const float* __restrict__ scale, const float* __restrict__ shift,
    const float* __restrict__ resid, int Co, int Ci) {

    const int L = LL;
    int b  = blockIdx.z;
    const float* Sb = S + (size_t)b * Ci * L;
    float*       Ob = out + (size_t)b * Co * L;
    const float* Rb = resid ? resid + (size_t)b * Co * L : nullptr;

    int tm = blockIdx.y * 128;
    int tn = blockIdx.x * 128;
    int tid = threadIdx.x;

    __shared__ float As[8][128];
    __shared__ float Bs[8][128];

    float acc[8][8];
#pragma unroll
    for (int i = 0; i < 8; ++i)
#pragma unroll
        for (int j = 0; j < 8; ++j) acc[i][j] = 0.f;

    int arow = tid >> 1;              // 0..127
    int acol = (tid & 1) * 4;         // 0 or 4
    int brow = tid >> 5;              // 0..7
    int bcol = (tid & 31) * 4;        // 0..124

    const float* Aptr = W  + (size_t)(tm + arow) * Ci + acol;
    const float* Bptr = Sb + (size_t)brow * L + tn + bcol;

    int mb = (tid >> 4) * 8;
    int nb = (tid & 15) * 8;

    for (int k0 = 0; k0 < Ci; k0 += 8) {
        float4 a4 = *(const float4*)(Aptr + k0);
        float4 b4 = *(const float4*)(Bptr + (size_t)k0 * L);
        __syncthreads();
        As[acol + 0][arow] = a4.x;
        As[acol + 1][arow] = a4.y;
        As[acol + 2][arow] = a4.z;
        As[acol + 3][arow] = a4.w;
        *(float4*)&Bs[brow][bcol] = b4;
        __syncthreads();
#pragma unroll
        for (int kk = 0; kk < 8; ++kk) {
            float av[8], bv[8];
            float4 t0 = *(const float4*)&As[kk][mb];
            float4 t1 = *(const float4*)&As[kk][mb + 4];
            av[0]=t0.x; av[1]=t0.y; av[2]=t0.z; av[3]=t0.w;
            av[4]=t1.x; av[5]=t1.y; av[6]=t1.z; av[7]=t1.w;
            float4 u0 = *(const float4*)&Bs[kk][nb];
            float4 u1 = *(const float4*)&Bs[kk][nb + 4];
            bv[0]=u0.x; bv[1]=u0.y; bv[2]=u0.z; bv[3]=u0.w;
            bv[4]=u1.x; bv[5]=u1.y; bv[6]=u1.z; bv[7]=u1.w;
#pragma unroll
            for (int i = 0; i < 8; ++i)
#pragma unroll
                for (int j = 0; j < 8; ++j)
                    acc[i][j] += av[i] * bv[j];
        }
    }

#pragma unroll
    for (int i = 0; i < 8; ++i) {
        int co = tm + mb + i;
        float sc = scale ? scale[co] : 1.0f;
        float sh = shift ? shift[co] : 0.0f;
        float*       op = Ob + (size_t)co * L + tn + nb;
        const float* rp = Rb ? Rb + (size_t)co * L + tn + nb : nullptr;
#pragma unroll
        for (int j = 0; j < 8; j += 4) {
            float4 o;
            o.x = acc[i][j + 0] * sc + sh;
            o.y = acc[i][j + 1] * sc + sh;
            o.z = acc[i][j + 2] * sc + sh;
            o.w = acc[i][j + 3] * sc + sh;
            if (rp) {
                float4 r = *(const float4*)(rp + j);
                o.x += r.x; o.y += r.y; o.z += r.z; o.w += r.w;
            }
            *(float4*)(op + j) = o;
        }
    }
}

// -------------------- M = k^T v per (b,h): 64x64x2048 ----------------------
__global__ void __launch_bounds__(256) kv_outer_k(
    const float* __restrict__ sk, const float* __restrict__ sv, float* __restrict__ M) {
    int bh = blockIdx.x;                       // 0..31
    int b = bh >> 3, h = bh & 7;
    size_t off = ((size_t)b * CC + (size_t)h * HD) * LL;
    const float* K = sk + off;
    const float* V = sv + off;

    __shared__ float Ks[64][65];
    __shared__ float Vs[64][65];

    float acc[4][4];
#pragma unroll
    for (int i = 0; i < 4; ++i)
#pragma unroll
        for (int j = 0; j < 4; ++j) acc[i][j] = 0.f;

    int tr = threadIdx.x >> 4;   // 0..15 (j block)
    int tc = threadIdx.x & 15;   // 0..15 (j' block)
    int row = threadIdx.x >> 2;          // 0..63
    int cb  = (threadIdx.x & 3) * 16;    // 0,16,32,48

    for (int l0 = 0; l0 < LL; l0 += 64) {
        __syncthreads();
#pragma unroll
        for (int u = 0; u < 16; u += 4) {
            float4 kv = *(const float4*)&K[(size_t)row * LL + l0 + cb + u];
            Ks[row][cb + u + 0] = kv.x; Ks[row][cb + u + 1] = kv.y;
            Ks[row][cb + u + 2] = kv.z; Ks[row][cb + u + 3] = kv.w;
            float4 vv = *(const float4*)&V[(size_t)row * LL + l0 + cb + u];
            Vs[row][cb + u + 0] = vv.x; Vs[row][cb + u + 1] = vv.y;
            Vs[row][cb + u + 2] = vv.z; Vs[row][cb + u + 3] = vv.w;
        }
        __syncthreads();
#pragma unroll
        for (int ll = 0; ll < 64; ++ll) {
            float a[4], c[4];
#pragma unroll
            for (int i = 0; i < 4; ++i) a[i] = Ks[tr * 4 + i][ll];
#pragma unroll
            for (int i = 0; i < 4; ++i) c[i] = Vs[tc * 4 + i][ll];
#pragma unroll
            for (int i = 0; i < 4; ++i)
#pragma unroll
                for (int j = 0; j < 4; ++j)
                    acc[i][j] += a[i] * c[j];
        }
    }
#pragma unroll
    for (int i = 0; i < 4; ++i)
#pragma unroll
        for (int j = 0; j < 4; ++j)
            M[((size_t)bh * HD + tr * 4 + i) * HD + tc * 4 + j] = acc[i][j];
}

// -------------------- o = q @ M, scale, lif_ss spike ------------------------
// For each (b,h): so[h*64+j', l] = spike( (sum_j q[j,l]*M[j,j']) * 0.125 / 1.5 - 1 )
__global__ void __launch_bounds__(256) qm_spike_k(
    const float* __restrict__ sq, const float* __restrict__ M, float* __restrict__ so) {
    int bh = blockIdx.y;
    int b = bh >> 3, h = bh & 7;
    int l = blockIdx.x * 256 + threadIdx.x;    // grid.x = 8 -> covers L=2048

    __shared__ float Ms[HD * HD];
#pragma unroll
    for (int u = 0; u < 16; ++u)
        Ms[u * 256 + threadIdx.x] = M[(size_t)bh * HD * HD + u * 256 + threadIdx.x];
    __syncthreads();

    size_t off = ((size_t)b * CC + (size_t)h * HD) * LL + l;
    const float* Q = sq + off;
    float acc[HD];
#pragma unroll
    for (int jp = 0; jp < HD; ++jp) acc[jp] = 0.f;

    for (int j = 0; j < HD; ++j) {
        float qv = Q[(size_t)j * LL];
#pragma unroll
        for (int jp = 0; jp < HD; ++jp)
            acc[jp] += qv * Ms[j * HD + jp];
    }

    float* O = so + off;
#pragma unroll
    for (int jp = 0; jp < HD; ++jp) {
        float o = acc[jp] * 0.125f;
        O[(size_t)jp * LL] = ((o / 1.5f - 1.f) >= 0.f) ? 1.f : 0.f;
    }
}

// ---------------------------------------------------------------------------
extern "C" void kernel_launch(void* const* d_in, const int* in_sizes, int n_in,
                              void* d_out, int out_size) {
    const float* x        = (const float*)d_in[0];
    const float* attn_bn  = (const float*)d_in[1];
    const float* q_w      = (const float*)d_in[2];
    const float* q_bn     = (const float*)d_in[3];
    const float* k_w      = (const float*)d_in[4];
    const float* k_bn     = (const float*)d_in[5];
    const float* v_w      = (const float*)d_in[6];
    const float* v_bn     = (const float*)d_in[7];
    const float* proj_w   = (const float*)d_in[8];
    const float* proj_b   = (const float*)d_in[9];
    const float* mlp_bn   = (const float*)d_in[10];
    const float* fc1_w    = (const float*)d_in[11];
    const float* fc1_b    = (const float*)d_in[12];
    const float* fc1_bn   = (const float*)d_in[13];
    const float* fc2_w    = (const float*)d_in[14];
    const float* fc2_b    = (const float*)d_in[15];
    float* out = (float*)d_out;

    float *xq, *y, *sq, *sk, *sv, *M, *so, *x1, *s2, *scale, *shift;
    cudaGetSymbolAddress((void**)&xq, g_xq);
    cudaGetSymbolAddress((void**)&y,  g_y);
    cudaGetSymbolAddress((void**)&sq, g_sq);
    cudaGetSymbolAddress((void**)&sk, g_sk);
    cudaGetSymbolAddress((void**)&sv, g_sv);
    cudaGetSymbolAddress((void**)&M,  g_M);
    cudaGetSymbolAddress((void**)&so, g_so);
    cudaGetSymbolAddress((void**)&x1, g_x1);
    cudaGetSymbolAddress((void**)&s2, g_s2);
    cudaGetSymbolAddress((void**)&scale, g_scale);
    cudaGetSymbolAddress((void**)&shift, g_shift);

    // fold BN params (+ fc1 bias into its BN)
    bnprep_k<<<2, 256>>>(attn_bn, nullptr, scale + 0 * 2048, shift + 0 * 2048, CC);
    bnprep_k<<<2, 256>>>(q_bn,    nullptr, scale + 1 * 2048, shift + 1 * 2048, CC);
    bnprep_k<<<2, 256>>>(k_bn,    nullptr, scale + 2 * 2048, shift + 2 * 2048, CC);
    bnprep_k<<<2, 256>>>(v_bn,    nullptr, scale + 3 * 2048, shift + 3 * 2048, CC);
    bnprep_k<<<2, 256>>>(mlp_bn,  nullptr, scale + 4 * 2048, shift + 4 * 2048, CC);
    bnprep_k<<<8, 256>>>(fc1_bn,  fc1_b,   scale + 5 * 2048, shift + 5 * 2048, HID);

    // attn input spikes
    lif_bn_k<<<4096, 256>>>(x, xq, scale + 0 * 2048, shift + 0 * 2048);

    dim3 g512(16, 4, 4);       // L/128, Co/128, B  (Co=512)
    dim3 g2048(16, 16, 4);     // Co=2048

    // q/k/v branches: GEMM + BN epilogue, then LIF over T
    gemm_bn_k<<<g512, 256>>>(q_w, xq, y, scale + 1 * 2048, shift + 1 * 2048, nullptr, CC, CC);
    lif_t_k<<<4096, 256>>>(y, sq, CC);
    gemm_bn_k<<<g512, 256>>>(k_w, xq, y, scale + 2 * 2048, shift + 2 * 2048, nullptr, CC, CC);
    lif_t_k<<<4096, 256>>>(y, sk, CC);
    gemm_bn_k<<<g512, 256>>>(v_w, xq, y, scale + 3 * 2048, shift + 3 * 2048, nullptr, CC, CC);
    lif_t_k<<<4096, 256>>>(y, sv, CC);

    // attention via (q k^T) v == q (k^T v)  (exact: binary operands, integer sums)
    kv_outer_k<<<32, 256>>>(sk, sv, M);
    qm_spike_k<<<dim3(8, 32), 256>>>(sq, M, so);

    // proj + residual
    gemm_bn_k<<<g512, 256>>>(proj_w, so, x1, nullptr, proj_b, x, CC, CC);

    // MLP
    lif_bn_k<<<4096, 256>>>(x1, xq, scale + 4 * 2048, shift + 4 * 2048);
    gemm_bn_k<<<g2048, 256>>>(fc1_w, xq, y, scale + 5 * 2048, shift + 5 * 2048, nullptr, HID, CC);
    lif_t_k<<<16384, 256>>>(y, s2, HID);
    gemm_bn_k<<<g512, 256>>>(fc2_w, s2, out, nullptr, fc2_b, x1, CC, HID);
}

// round 4
// speedup vs baseline: 2.9236x; 2.9236x over previous
#include <cuda_runtime.h>
#include <cuda_bf16.h>
#include <cstdint>
#include <cstddef>

// ---------------------------------------------------------------------------
// SpikingTransformerBlock, mma.sync bf16 path (base sm_100 compatible)
// B=4, C=512, T=4, N=512, L=2048, HID=2048, H=8, d=64
//
// W(fp32) = W_hi + W_lo + W_lo2 (3x bf16, exact to ~2^-26) ; spikes {0,1} exact
// in bf16; fp32 accumulation => effectively fp32-exact GEMMs on tensor cores.
// Attention uses exact reassociation o = q (k^T v).
// ---------------------------------------------------------------------------

#define BB 4
#define CC 512
#define TT 4
#define NNv 512
#define LLv 2048
#define HIDN 2048
#define NH 8
#define HD 64

// GEMM tiling
#define MT 128
#define NT 128
#define KCH 64
#define A_TERM_BYTES (MT * KCH * 2)           // 16384
#define A_BYTES (3 * A_TERM_BYTES)            // 49152
#define B_BYTES (NT * KCH * 2)                // 16384
#define STAGE_BYTES (A_BYTES + B_BYTES)       // 65536
#define DYN_SMEM (2 * STAGE_BYTES)            // 131072

#define SW(o) ((o) ^ (((o) >> 3) & 0x70))

// -------------------- device scratch ---------------------------------------
__device__ float g_y [(size_t)BB * HIDN * LLv];   // gemm out (pre-LIF), 64MB
__device__ float g_sq[(size_t)BB * CC * LLv];
__device__ float g_sk[(size_t)BB * CC * LLv];
__device__ float g_sv[(size_t)BB * CC * LLv];
__device__ float g_x1[(size_t)BB * CC * LLv];
__device__ float g_M [(size_t)BB * NH * HD * HD];
__device__ __nv_bfloat16 g_xqT[(size_t)BB * LLv * CC];
__device__ __nv_bfloat16 g_soT[(size_t)BB * LLv * CC];
__device__ __nv_bfloat16 g_s2T[(size_t)BB * LLv * HIDN];
__device__ __nv_bfloat16 g_w[9437184];            // 3-way split weights
__device__ float g_scale[6 * 2048];
__device__ float g_shift[6 * 2048];

// -------------------- helpers ----------------------------------------------
__device__ __forceinline__ uint32_t smem_u32(const void* p) {
    uint32_t a;
    asm("{ .reg .u64 t; cvta.to.shared.u64 t, %1; cvt.u32.u64 %0, t; }" : "=r"(a) : "l"(p));
    return a;
}
#define CP16(sa, gp) \
    asm volatile("cp.async.cg.shared.global [%0], [%1], 16;" :: "r"(sa), "l"(gp) : "memory")
#define CP_COMMIT() asm volatile("cp.async.commit_group;" ::: "memory")
#define CP_WAIT1() asm volatile("cp.async.wait_group 1;" ::: "memory")
#define CP_WAIT0() asm volatile("cp.async.wait_group 0;" ::: "memory")

__device__ __forceinline__ void ldm_x4(uint32_t& r0, uint32_t& r1, uint32_t& r2, uint32_t& r3,
                                       uint32_t addr) {
    asm volatile("ldmatrix.sync.aligned.m8n8.x4.shared.b16 {%0,%1,%2,%3}, [%4];"
                 : "=r"(r0), "=r"(r1), "=r"(r2), "=r"(r3) : "r"(addr));
}
__device__ __forceinline__ void mma16816(float* c, uint32_t a0, uint32_t a1, uint32_t a2,
                                         uint32_t a3, uint32_t b0, uint32_t b1) {
    asm volatile("mma.sync.aligned.m16n8k16.row.col.f32.bf16.bf16.f32 "
                 "{%0,%1,%2,%3},{%4,%5,%6,%7},{%8,%9},{%0,%1,%2,%3};"
                 : "+f"(c[0]), "+f"(c[1]), "+f"(c[2]), "+f"(c[3])
                 : "r"(a0), "r"(a1), "r"(a2), "r"(a3), "r"(b0), "r"(b1));
}

// -------------------- BN fold ----------------------------------------------
__global__ void bnprep_k(const float* __restrict__ p, const float* __restrict__ bias,
                         float* __restrict__ scale, float* __restrict__ shift, int Cdim) {
    int c = blockIdx.x * blockDim.x + threadIdx.x;
    if (c >= Cdim) return;
    float g = p[c], be = p[Cdim + c], m = p[2 * Cdim + c], va = p[3 * Cdim + c];
    float inv = g / sqrtf(va + 1e-5f);
    float sh = be - m * inv;
    if (bias) sh += bias[c] * inv;
    scale[c] = inv; shift[c] = sh;
}

// -------------------- weight 3-way bf16 split -------------------------------
__global__ void wsplit_k(const float* __restrict__ w, __nv_bfloat16* __restrict__ o, int sz) {
    int i = blockIdx.x * 256 + threadIdx.x;
    if (i >= sz) return;
    float x = w[i];
    __nv_bfloat16 h = __float2bfloat16(x);
    float r = x - __bfloat162float(h);
    __nv_bfloat16 m = __float2bfloat16(r);
    float r2 = r - __bfloat162float(m);
    o[i] = h; o[sz + i] = m; o[2 * sz + i] = __float2bfloat16(r2);
}

// -------------------- LIF (+opt BN) -> transposed bf16 spikes ---------------
__global__ void lif_tr_k(const float* __restrict__ in, __nv_bfloat16* __restrict__ outT,
                         const float* __restrict__ scale, const float* __restrict__ shift,
                         int Cdim) {
    __shared__ float tile[TT][32][33];
    int b = blockIdx.z, c0 = blockIdx.y * 32, n0 = blockIdx.x * 32;
    int tx = threadIdx.x, ty = threadIdx.y;
#pragma unroll
    for (int i = 0; i < 4; ++i) {
        int c = c0 + ty + 8 * i;
        float sc = scale ? scale[c] : 1.f;
        float sh = shift ? shift[c] : 0.f;
        size_t base = ((size_t)b * Cdim + c) * LLv + n0 + tx;
        float v = 0.f;
#pragma unroll
        for (int t = 0; t < TT; ++t) {
            float xv = in[base + (size_t)t * NNv] * sc + sh;
            v += (xv - v) / 1.5f;
            float sp = (v >= 1.f) ? 1.f : 0.f;
            tile[t][ty + 8 * i][tx] = sp;
            v = (v >= 1.f) ? 0.f : v;
        }
    }
    __syncthreads();
#pragma unroll
    for (int t = 0; t < TT; ++t)
#pragma unroll
        for (int i = 0; i < 4; ++i) {
            int l = t * NNv + n0 + ty + 8 * i;
            outT[((size_t)b * LLv + l) * Cdim + c0 + tx] =
                __float2bfloat16(tile[t][tx][ty + 8 * i]);
        }
}

// -------------------- LIF -> fp32 spikes [C,L] ------------------------------
__global__ void lif_t_k(const float* __restrict__ y, float* __restrict__ s, int Cdim) {
    int idx = blockIdx.x * blockDim.x + threadIdx.x;
    int n = idx & (NNv - 1);
    int rest = idx >> 9;
    int c = rest % Cdim;
    int b = rest / Cdim;
    size_t base = (((size_t)b * Cdim + c) * LLv) + n;
    float v = 0.f;
#pragma unroll
    for (int t = 0; t < TT; ++t) {
        float xv = y[base + (size_t)t * NNv];
        v += (xv - v) / 1.5f;
        float sp = (v >= 1.0f) ? 1.f : 0.f;
        s[base + (size_t)t * NNv] = sp;
        v = (v >= 1.0f) ? 0.f : v;
    }
}

// -------------------- mma.sync GEMM ----------------------------------------
// out[b] = (3-term bf16 W) @ S^T[b] (+scale/shift per row) (+resid)
// Wspl: [3][Co][Ci] bf16, k-major; BT: [B][L][Ci] bf16; out fp32 [B][Co][L]
__global__ void __launch_bounds__(256, 1) gemm_mma_k(
    const __nv_bfloat16* __restrict__ Wspl, const __nv_bfloat16* __restrict__ BT,
    float* __restrict__ out, const float* __restrict__ scale, const float* __restrict__ shift,
    const float* __restrict__ resid, int Co, int Ci) {

    extern __shared__ __align__(16) char smem[];
    uint32_t sb = smem_u32(smem);
    int tid = threadIdx.x;
    int lane = tid & 31, w = tid >> 5;
    int wm = w & 1, wn = w >> 1;          // 2 x 4 warp grid, warp tile 64x32

    int b = blockIdx.z;
    int tm = blockIdx.y * MT;
    int tn = blockIdx.x * NT;
    const __nv_bfloat16* Bt = BT + (size_t)b * LLv * Ci;
    const size_t termstride = (size_t)Co * Ci;
    const int KC = Ci / KCH;

    float acc[4][4][4];
#pragma unroll
    for (int i = 0; i < 4; ++i)
#pragma unroll
        for (int j = 0; j < 4; ++j)
#pragma unroll
            for (int r = 0; r < 4; ++r) acc[i][j][r] = 0.f;

    auto issue_loads = [&](int c) {
        uint32_t base = sb + (c & 1) * STAGE_BYTES;
        int k0 = c * KCH;
#pragma unroll
        for (int i = 0; i < 12; ++i) {                   // A: 3 terms x 128 x 8 chunks
            int idx = i * 256 + tid;
            int term = idx >> 10;
            int within = idx & 1023;
            int row = within >> 3, c16 = within & 7;
            uint32_t o = (uint32_t)(row * 128 + c16 * 16);
            CP16(base + term * A_TERM_BYTES + SW(o),
                 Wspl + (size_t)term * termstride + (size_t)(tm + row) * Ci + k0 + c16 * 8);
        }
#pragma unroll
        for (int i = 0; i < 4; ++i) {                    // B: 128 x 8 chunks
            int idx = i * 256 + tid;
            int row = idx >> 3, c16 = idx & 7;
            uint32_t o = (uint32_t)(row * 128 + c16 * 16);
            CP16(base + A_BYTES + SW(o),
                 Bt + (size_t)(tn + row) * Ci + k0 + c16 * 8);
        }
        CP_COMMIT();
    };

    issue_loads(0);
    issue_loads(1);

    // ldmatrix lane addressing (relative offsets within a tile)
    int sub = lane >> 3;                 // 0..3
    int lrow = lane & 7;
    // A frags: (sub&1) -> m-half, (sub>>1) -> k-half   => regs [m0k0, m1k0, m0k1, m1k1]
    // B frags: (sub&1) -> k-half, (sub>>1) -> n-half   => regs [n0k0, n0k1, n1k0, n1k1]

    for (int c = 0; c < KC; ++c) {
        uint32_t base = sb + (c & 1) * STAGE_BYTES;
        if (c < KC - 1) CP_WAIT1(); else CP_WAIT0();
        __syncthreads();

        uint32_t abase = base;
        uint32_t bbase = base + A_BYTES;
#pragma unroll
        for (int ks = 0; ks < 4; ++ks) {
            // B fragments: n32 per warp = 2 ldmatrix.x4 (each covers n16)
            uint32_t bfr[8];
#pragma unroll
            for (int ni = 0; ni < 2; ++ni) {
                int n = wn * 32 + ni * 16 + (sub >> 1) * 8 + lrow;
                uint32_t o = (uint32_t)(n * 128 + ks * 32 + (sub & 1) * 16);
                ldm_x4(bfr[ni * 4 + 0], bfr[ni * 4 + 1], bfr[ni * 4 + 2], bfr[ni * 4 + 3],
                       bbase + SW(o));
            }
#pragma unroll
            for (int term = 0; term < 3; ++term) {
                uint32_t tb = abase + term * A_TERM_BYTES;
                uint32_t af[4][4];
#pragma unroll
                for (int mi = 0; mi < 4; ++mi) {
                    int m = wm * 64 + mi * 16 + (sub & 1) * 8 + lrow;
                    uint32_t o = (uint32_t)(m * 128 + ks * 32 + (sub >> 1) * 16);
                    ldm_x4(af[mi][0], af[mi][1], af[mi][2], af[mi][3], tb + SW(o));
                }
#pragma unroll
                for (int mi = 0; mi < 4; ++mi)
#pragma unroll
                    for (int nj = 0; nj < 4; ++nj)
                        mma16816(acc[mi][nj], af[mi][0], af[mi][1], af[mi][2], af[mi][3],
                                 bfr[(nj >> 1) * 4 + (nj & 1) * 2],
                                 bfr[(nj >> 1) * 4 + (nj & 1) * 2 + 1]);
            }
        }
        __syncthreads();
        if (c + 2 < KC) issue_loads(c + 2);
    }

    // epilogue
#pragma unroll
    for (int mi = 0; mi < 4; ++mi) {
#pragma unroll
        for (int h = 0; h < 2; ++h) {
            int co = tm + wm * 64 + mi * 16 + h * 8 + (lane >> 2);
            float scv = scale ? scale[co] : 1.f;
            float shv = shift ? shift[co] : 0.f;
            float* op = out + ((size_t)b * Co + co) * LLv + tn;
            const float* rp = resid ? resid + ((size_t)b * Co + co) * LLv + tn : nullptr;
#pragma unroll
            for (int nj = 0; nj < 4; ++nj) {
                int col = wn * 32 + nj * 8 + (lane & 3) * 2;
                float2 o;
                o.x = acc[mi][nj][h * 2 + 0] * scv + shv;
                o.y = acc[mi][nj][h * 2 + 1] * scv + shv;
                if (rp) {
                    float2 rv = *(const float2*)(rp + col);
                    o.x += rv.x; o.y += rv.y;
                }
                *(float2*)(op + col) = o;
            }
        }
    }
}

// -------------------- M = k^T v per (b,h) ----------------------------------
__global__ void __launch_bounds__(256) kv_outer_k(
    const float* __restrict__ sk, const float* __restrict__ sv, float* __restrict__ M) {
    int bh = blockIdx.x;
    int b = bh >> 3, h = bh & 7;
    size_t off = ((size_t)b * CC + (size_t)h * HD) * LLv;
    const float* K = sk + off;
    const float* V = sv + off;
    __shared__ float Ks[64][65];
    __shared__ float Vs[64][65];
    float acc[4][4];
#pragma unroll
    for (int i = 0; i < 4; ++i)
#pragma unroll
        for (int j = 0; j < 4; ++j) acc[i][j] = 0.f;
    int tr = threadIdx.x >> 4, tc = threadIdx.x & 15;
    int row = threadIdx.x >> 2, cb = (threadIdx.x & 3) * 16;
    for (int l0 = 0; l0 < LLv; l0 += 64) {
        __syncthreads();
#pragma unroll
        for (int u = 0; u < 16; u += 4) {
            float4 kv = *(const float4*)&K[(size_t)row * LLv + l0 + cb + u];
            Ks[row][cb + u] = kv.x; Ks[row][cb + u + 1] = kv.y;
            Ks[row][cb + u + 2] = kv.z; Ks[row][cb + u + 3] = kv.w;
            float4 vv = *(const float4*)&V[(size_t)row * LLv + l0 + cb + u];
            Vs[row][cb + u] = vv.x; Vs[row][cb + u + 1] = vv.y;
            Vs[row][cb + u + 2] = vv.z; Vs[row][cb + u + 3] = vv.w;
        }
        __syncthreads();
#pragma unroll
        for (int ll = 0; ll < 64; ++ll) {
            float a[4], c[4];
#pragma unroll
            for (int i = 0; i < 4; ++i) a[i] = Ks[tr * 4 + i][ll];
#pragma unroll
            for (int i = 0; i < 4; ++i) c[i] = Vs[tc * 4 + i][ll];
#pragma unroll
            for (int i = 0; i < 4; ++i)
#pragma unroll
                for (int j = 0; j < 4; ++j) acc[i][j] += a[i] * c[j];
        }
    }
#pragma unroll
    for (int i = 0; i < 4; ++i)
#pragma unroll
        for (int j = 0; j < 4; ++j)
            M[((size_t)bh * HD + tr * 4 + i) * HD + tc * 4 + j] = acc[i][j];
}

// -------------------- o = q @ M -> spike -> soT bf16 [B,L,C] ----------------
__global__ void __launch_bounds__(256) qm_spike_k(
    const float* __restrict__ sq, const float* __restrict__ M, __nv_bfloat16* __restrict__ soT) {
    int bh = blockIdx.y;
    int b = bh >> 3, h = bh & 7;
    int l = blockIdx.x * 256 + threadIdx.x;
    __shared__ float Ms[HD * HD];
#pragma unroll
    for (int u = 0; u < 16; ++u)
        Ms[u * 256 + threadIdx.x] = M[(size_t)bh * HD * HD + u * 256 + threadIdx.x];
    __syncthreads();
    size_t off = ((size_t)b * CC + (size_t)h * HD) * LLv + l;
    const float* Q = sq + off;
    float acc[HD];
#pragma unroll
    for (int jp = 0; jp < HD; ++jp) acc[jp] = 0.f;
    for (int j = 0; j < HD; ++j) {
        float qv = Q[(size_t)j * LLv];
#pragma unroll
        for (int jp = 0; jp < HD; ++jp) acc[jp] += qv * Ms[j * HD + jp];
    }
    __nv_bfloat16* O = soT + ((size_t)b * LLv + l) * CC + h * HD;
#pragma unroll
    for (int jp = 0; jp < HD; ++jp) {
        float o = acc[jp] * 0.125f;
        O[jp] = __float2bfloat16(((o / 1.5f - 1.f) >= 0.f) ? 1.f : 0.f);
    }
}

// ---------------------------------------------------------------------------
extern "C" void kernel_launch(void* const* d_in, const int* in_sizes, int n_in,
                              void* d_out, int out_size) {
    const float* x       = (const float*)d_in[0];
    const float* attn_bn = (const float*)d_in[1];
    const float* q_w     = (const float*)d_in[2];
    const float* q_bn    = (const float*)d_in[3];
    const float* k_w     = (const float*)d_in[4];
    const float* k_bn    = (const float*)d_in[5];
    const float* v_w     = (const float*)d_in[6];
    const float* v_bn    = (const float*)d_in[7];
    const float* proj_w  = (const float*)d_in[8];
    const float* proj_b  = (const float*)d_in[9];
    const float* mlp_bn  = (const float*)d_in[10];
    const float* fc1_w   = (const float*)d_in[11];
    const float* fc1_b   = (const float*)d_in[12];
    const float* fc1_bn  = (const float*)d_in[13];
    const float* fc2_w   = (const float*)d_in[14];
    const float* fc2_b   = (const float*)d_in[15];
    float* out = (float*)d_out;

    float *y, *sq, *sk, *sv, *x1, *M, *scale, *shift;
    __nv_bfloat16 *xqT, *soT, *s2T, *w;
    cudaGetSymbolAddress((void**)&y,   g_y);
    cudaGetSymbolAddress((void**)&sq,  g_sq);
    cudaGetSymbolAddress((void**)&sk,  g_sk);
    cudaGetSymbolAddress((void**)&sv,  g_sv);
    cudaGetSymbolAddress((void**)&x1,  g_x1);
    cudaGetSymbolAddress((void**)&M,   g_M);
    cudaGetSymbolAddress((void**)&scale, g_scale);
    cudaGetSymbolAddress((void**)&shift, g_shift);
    cudaGetSymbolAddress((void**)&xqT, g_xqT);
    cudaGetSymbolAddress((void**)&soT, g_soT);
    cudaGetSymbolAddress((void**)&s2T, g_s2T);
    cudaGetSymbolAddress((void**)&w,   g_w);

    cudaFuncSetAttribute(gemm_mma_k, cudaFuncAttributeMaxDynamicSharedMemorySize, DYN_SMEM);

    const int SZ = CC * CC;
    const int SZH = HIDN * CC;
    __nv_bfloat16* wq  = w;
    __nv_bfloat16* wk  = w + 3 * (size_t)SZ;
    __nv_bfloat16* wv  = w + 6 * (size_t)SZ;
    __nv_bfloat16* wp  = w + 9 * (size_t)SZ;
    __nv_bfloat16* wf1 = w + 12 * (size_t)SZ;
    __nv_bfloat16* wf2 = wf1 + 3 * (size_t)SZH;

    bnprep_k<<<2, 256>>>(attn_bn, nullptr, scale + 0 * 2048, shift + 0 * 2048, CC);
    bnprep_k<<<2, 256>>>(q_bn,    nullptr, scale + 1 * 2048, shift + 1 * 2048, CC);
    bnprep_k<<<2, 256>>>(k_bn,    nullptr, scale + 2 * 2048, shift + 2 * 2048, CC);
    bnprep_k<<<2, 256>>>(v_bn,    nullptr, scale + 3 * 2048, shift + 3 * 2048, CC);
    bnprep_k<<<2, 256>>>(mlp_bn,  nullptr, scale + 4 * 2048, shift + 4 * 2048, CC);
    bnprep_k<<<8, 256>>>(fc1_bn,  fc1_b,   scale + 5 * 2048, shift + 5 * 2048, HIDN);

    wsplit_k<<<SZ / 256, 256>>>(q_w, wq, SZ);
    wsplit_k<<<SZ / 256, 256>>>(k_w, wk, SZ);
    wsplit_k<<<SZ / 256, 256>>>(v_w, wv, SZ);
    wsplit_k<<<SZ / 256, 256>>>(proj_w, wp, SZ);
    wsplit_k<<<SZH / 256, 256>>>(fc1_w, wf1, SZH);
    wsplit_k<<<SZH / 256, 256>>>(fc2_w, wf2, SZH);

    dim3 ltr(32, 8);
    dim3 gtr512(16, 16, BB);
    dim3 gtr2048(16, 64, BB);
    dim3 gg512(LLv / NT, CC / MT, BB);     // (16,4,4)
    dim3 gg2048(LLv / NT, HIDN / MT, BB);  // (16,16,4)

    // attn input spikes (BN_attn + LIF) -> xqT bf16 [B,L,C]
    lif_tr_k<<<gtr512, ltr>>>(x, xqT, scale + 0 * 2048, shift + 0 * 2048, CC);

    // q/k/v
    gemm_mma_k<<<gg512, 256, DYN_SMEM>>>(wq, xqT, y, scale + 1 * 2048, shift + 1 * 2048, nullptr, CC, CC);
    lif_t_k<<<4096, 256>>>(y, sq, CC);
    gemm_mma_k<<<gg512, 256, DYN_SMEM>>>(wk, xqT, y, scale + 2 * 2048, shift + 2 * 2048, nullptr, CC, CC);
    lif_t_k<<<4096, 256>>>(y, sk, CC);
    gemm_mma_k<<<gg512, 256, DYN_SMEM>>>(wv, xqT, y, scale + 3 * 2048, shift + 3 * 2048, nullptr, CC, CC);
    lif_t_k<<<4096, 256>>>(y, sv, CC);

    // attention: exact q (k^T v)
    kv_outer_k<<<32, 256>>>(sk, sv, M);
    qm_spike_k<<<dim3(8, 32), 256>>>(sq, M, soT);

    // proj + residual
    gemm_mma_k<<<gg512, 256, DYN_SMEM>>>(wp, soT, x1, nullptr, proj_b, x, CC, CC);

    // MLP
    lif_tr_k<<<gtr512, ltr>>>(x1, xqT, scale + 4 * 2048, shift + 4 * 2048, CC);
    gemm_mma_k<<<gg2048, 256, DYN_SMEM>>>(wf1, xqT, y, scale + 5 * 2048, shift + 5 * 2048, nullptr, HIDN, CC);
    lif_tr_k<<<gtr2048, ltr>>>(y, s2T, nullptr, nullptr, HIDN);
    gemm_mma_k<<<gg512, 256, DYN_SMEM>>>(wf2, s2T, out, nullptr, fc2_b, x1, CC, HIDN);
}

// round 6
// speedup vs baseline: 3.6069x; 1.2337x over previous
#include <cuda_runtime.h>
#include <cuda_fp16.h>
#include <cuda_bf16.h>
#include <cstdint>
#include <cstddef>

// ---------------------------------------------------------------------------
// SpikingTransformerBlock, mma.sync fp16 2-term path (base sm_100 compatible)
// B=4, C=512, T=4, N=512, L=2048, HID=2048, H=8, d=64
//
// W(fp32) = W_hi + W_lo (2x fp16; residual ~3e-8 abs ~ fp32 noise floor);
// spikes {0,1} exact in fp16; fp32 accumulation on tensor cores.
// Attention uses exact reassociation o = q (k^T v).
// GEMM: 128x256 CTA tile, 64x64 warp tile, 3-stage cp.async pipeline.
// ---------------------------------------------------------------------------

#define BB 4
#define CC 512
#define TT 4
#define NNv 512
#define LLv 2048
#define HIDN 2048
#define NH 8
#define HD 64

#define MT 128
#define NT 256
#define KCH 64
#define TERMS 2
#define A_TERM_BYTES (MT * KCH * 2)           // 16384
#define A_BYTES (TERMS * A_TERM_BYTES)        // 32768
#define B_BYTES (NT * KCH * 2)                // 32768
#define STAGE_BYTES (A_BYTES + B_BYTES)       // 65536
#define NSTAGE 3
#define DYN_SMEM (NSTAGE * STAGE_BYTES)       // 196608

#define SW(o) ((o) ^ (((o) >> 3) & 0x70))

// -------------------- device scratch ---------------------------------------
__device__ float g_y [(size_t)BB * HIDN * LLv];
__device__ float g_sq[(size_t)BB * CC * LLv];
__device__ float g_sk[(size_t)BB * CC * LLv];
__device__ float g_sv[(size_t)BB * CC * LLv];
__device__ float g_x1[(size_t)BB * CC * LLv];
__device__ float g_M [(size_t)BB * NH * HD * HD];
__device__ __half g_xqT[(size_t)BB * LLv * CC];
__device__ __half g_soT[(size_t)BB * LLv * CC];
__device__ __half g_s2T[(size_t)BB * LLv * HIDN];
__device__ __half g_w[6291456];                   // 2-way split weights
__device__ float g_scale[6 * 2048];
__device__ float g_shift[6 * 2048];

// -------------------- helpers ----------------------------------------------
__device__ __forceinline__ uint32_t smem_u32(const void* p) {
    uint32_t a;
    asm("{ .reg .u64 t; cvta.to.shared.u64 t, %1; cvt.u32.u64 %0, t; }" : "=r"(a) : "l"(p));
    return a;
}
#define CP16(sa, gp) \
    asm volatile("cp.async.cg.shared.global [%0], [%1], 16;" :: "r"(sa), "l"(gp) : "memory")
#define CP_COMMIT() asm volatile("cp.async.commit_group;" ::: "memory")
#define CP_WAIT1() asm volatile("cp.async.wait_group 1;" ::: "memory")
#define CP_WAIT0() asm volatile("cp.async.wait_group 0;" ::: "memory")

__device__ __forceinline__ void ldm_x4(uint32_t& r0, uint32_t& r1, uint32_t& r2, uint32_t& r3,
                                       uint32_t addr) {
    asm volatile("ldmatrix.sync.aligned.m8n8.x4.shared.b16 {%0,%1,%2,%3}, [%4];"
                 : "=r"(r0), "=r"(r1), "=r"(r2), "=r"(r3) : "r"(addr));
}
__device__ __forceinline__ void mma16816(float* c, uint32_t a0, uint32_t a1, uint32_t a2,
                                         uint32_t a3, uint32_t b0, uint32_t b1) {
    asm volatile("mma.sync.aligned.m16n8k16.row.col.f32.f16.f16.f32 "
                 "{%0,%1,%2,%3},{%4,%5,%6,%7},{%8,%9},{%0,%1,%2,%3};"
                 : "+f"(c[0]), "+f"(c[1]), "+f"(c[2]), "+f"(c[3])
                 : "r"(a0), "r"(a1), "r"(a2), "r"(a3), "r"(b0), "r"(b1));
}

// -------------------- BN fold ----------------------------------------------
__global__ void bnprep_k(const float* __restrict__ p, const float* __restrict__ bias,
                         float* __restrict__ scale, float* __restrict__ shift, int Cdim) {
    int c = blockIdx.x * blockDim.x + threadIdx.x;
    if (c >= Cdim) return;
    float g = p[c], be = p[Cdim + c], m = p[2 * Cdim + c], va = p[3 * Cdim + c];
    float inv = g / sqrtf(va + 1e-5f);
    float sh = be - m * inv;
    if (bias) sh += bias[c] * inv;
    scale[c] = inv; shift[c] = sh;
}

// -------------------- weight 2-way fp16 split -------------------------------
__global__ void wsplit_k(const float* __restrict__ w, __half* __restrict__ o, int sz) {
    int i = blockIdx.x * 256 + threadIdx.x;
    if (i >= sz) return;
    float x = w[i];
    __half h = __float2half_rn(x);
    float r = x - __half2float(h);
    o[i] = h; o[sz + i] = __float2half_rn(r);
}

// -------------------- LIF (+opt BN) -> transposed fp16 spikes ---------------
__global__ void lif_tr_k(const float* __restrict__ in, __half* __restrict__ outT,
                         const float* __restrict__ scale, const float* __restrict__ shift,
                         int Cdim) {
    __shared__ float tile[TT][32][33];
    int b = blockIdx.z, c0 = blockIdx.y * 32, n0 = blockIdx.x * 32;
    int tx = threadIdx.x, ty = threadIdx.y;
#pragma unroll
    for (int i = 0; i < 4; ++i) {
        int c = c0 + ty + 8 * i;
        float sc = scale ? scale[c] : 1.f;
        float sh = shift ? shift[c] : 0.f;
        size_t base = ((size_t)b * Cdim + c) * LLv + n0 + tx;
        float v = 0.f;
#pragma unroll
        for (int t = 0; t < TT; ++t) {
            float xv = in[base + (size_t)t * NNv] * sc + sh;
            v += (xv - v) / 1.5f;
            float sp = (v >= 1.f) ? 1.f : 0.f;
            tile[t][ty + 8 * i][tx] = sp;
            v = (v >= 1.f) ? 0.f : v;
        }
    }
    __syncthreads();
#pragma unroll
    for (int t = 0; t < TT; ++t)
#pragma unroll
        for (int i = 0; i < 4; ++i) {
            int l = t * NNv + n0 + ty + 8 * i;
            outT[((size_t)b * LLv + l) * Cdim + c0 + tx] =
                __float2half_rn(tile[t][tx][ty + 8 * i]);
        }
}

// -------------------- LIF -> fp32 spikes [C,L] ------------------------------
__global__ void lif_t_k(const float* __restrict__ y, float* __restrict__ s, int Cdim) {
    int idx = blockIdx.x * blockDim.x + threadIdx.x;
    int n = idx & (NNv - 1);
    int rest = idx >> 9;
    int c = rest % Cdim;
    int b = rest / Cdim;
    size_t base = (((size_t)b * Cdim + c) * LLv) + n;
    float v = 0.f;
#pragma unroll
    for (int t = 0; t < TT; ++t) {
        float xv = y[base + (size_t)t * NNv];
        v += (xv - v) / 1.5f;
        float sp = (v >= 1.0f) ? 1.f : 0.f;
        s[base + (size_t)t * NNv] = sp;
        v = (v >= 1.0f) ? 0.f : v;
    }
}

// -------------------- mma.sync GEMM ----------------------------------------
// out[b] = (2-term fp16 W) @ S^T[b] (+scale/shift per row) (+resid)
// Wspl: [2][Co][Ci] fp16 k-major; BT: [B][L][Ci] fp16; out fp32 [B][Co][L]
// 128x256 CTA tile, 8 warps in 2x4 grid of 64x64 warp tiles, 3-stage pipeline.
__global__ void __launch_bounds__(256, 1) gemm_mma_k(
    const __half* __restrict__ Wspl, const __half* __restrict__ BT,
    float* __restrict__ out, const float* __restrict__ scale, const float* __restrict__ shift,
    const float* __restrict__ resid, int Co, int Ci) {

    extern __shared__ __align__(16) char smem[];
    uint32_t sb = smem_u32(smem);
    int tid = threadIdx.x;
    int lane = tid & 31, w = tid >> 5;
    int wm = w & 1, wn = w >> 1;          // 2 x 4 warp grid, warp tile 64x64

    int b = blockIdx.z;
    int tm = blockIdx.y * MT;
    int tn = blockIdx.x * NT;
    const __half* Bt = BT + (size_t)b * LLv * Ci;
    const size_t termstride = (size_t)Co * Ci;
    const int KC = Ci / KCH;

    float acc[4][8][4];
#pragma unroll
    for (int i = 0; i < 4; ++i)
#pragma unroll
        for (int j = 0; j < 8; ++j)
#pragma unroll
            for (int r = 0; r < 4; ++r) acc[i][j][r] = 0.f;

    auto issue_loads = [&](int c) {
        uint32_t base = sb + (uint32_t)(c % NSTAGE) * STAGE_BYTES;
        int k0 = c * KCH;
#pragma unroll
        for (int i = 0; i < 8; ++i) {                    // A: 2 terms x 128 x 8 chunks
            int idx = i * 256 + tid;
            int term = idx >> 10;
            int within = idx & 1023;
            int row = within >> 3, c16 = within & 7;
            uint32_t o = (uint32_t)(row * 128 + c16 * 16);
            CP16(base + term * A_TERM_BYTES + SW(o),
                 Wspl + (size_t)term * termstride + (size_t)(tm + row) * Ci + k0 + c16 * 8);
        }
#pragma unroll
        for (int i = 0; i < 8; ++i) {                    // B: 256 x 8 chunks
            int idx = i * 256 + tid;
            int row = idx >> 3, c16 = idx & 7;
            uint32_t o = (uint32_t)(row * 128 + c16 * 16);
            CP16(base + A_BYTES + SW(o),
                 Bt + (size_t)(tn + row) * Ci + k0 + c16 * 8);
        }
        CP_COMMIT();
    };

    issue_loads(0);
    issue_loads(1);

    int sub = lane >> 3;                 // 0..3
    int lrow = lane & 7;
    // A frags: (sub&1)->m-half, (sub>>1)->k-half  => regs [m0k0, m1k0, m0k1, m1k1]
    // B frags: (sub&1)->k-half, (sub>>1)->n-half  => regs [n0k0, n0k1, n1k0, n1k1]

    for (int c = 0; c < KC; ++c) {
        uint32_t base = sb + (uint32_t)(c % NSTAGE) * STAGE_BYTES;
        if (c < KC - 1) CP_WAIT1(); else CP_WAIT0();
        __syncthreads();
        if (c + 2 < KC) issue_loads(c + 2);   // buffer (c+2)%3 fully consumed at iter c-1

        uint32_t abase = base;
        uint32_t bbase = base + A_BYTES;
#pragma unroll
        for (int ks = 0; ks < 4; ++ks) {
            uint32_t bfr[4][4];
#pragma unroll
            for (int ni = 0; ni < 4; ++ni) {
                int n = wn * 64 + ni * 16 + (sub >> 1) * 8 + lrow;
                uint32_t o = (uint32_t)(n * 128 + ks * 32 + (sub & 1) * 16);
                ldm_x4(bfr[ni][0], bfr[ni][1], bfr[ni][2], bfr[ni][3], bbase + SW(o));
            }
#pragma unroll
            for (int term = 0; term < TERMS; ++term) {
                uint32_t tb = abase + term * A_TERM_BYTES;
                uint32_t af[4][4];
#pragma unroll
                for (int mi = 0; mi < 4; ++mi) {
                    int m = wm * 64 + mi * 16 + (sub & 1) * 8 + lrow;
                    uint32_t o = (uint32_t)(m * 128 + ks * 32 + (sub >> 1) * 16);
                    ldm_x4(af[mi][0], af[mi][1], af[mi][2], af[mi][3], tb + SW(o));
                }
#pragma unroll
                for (int mi = 0; mi < 4; ++mi)
#pragma unroll
                    for (int nj = 0; nj < 8; ++nj)
                        mma16816(acc[mi][nj], af[mi][0], af[mi][1], af[mi][2], af[mi][3],
                                 bfr[nj >> 1][(nj & 1) * 2],
                                 bfr[nj >> 1][(nj & 1) * 2 + 1]);
            }
        }
    }

    // epilogue
#pragma unroll
    for (int mi = 0; mi < 4; ++mi) {
#pragma unroll
        for (int h = 0; h < 2; ++h) {
            int co = tm + wm * 64 + mi * 16 + h * 8 + (lane >> 2);
            float scv = scale ? scale[co] : 1.f;
            float shv = shift ? shift[co] : 0.f;
            float* op = out + ((size_t)b * Co + co) * LLv + tn;
            const float* rp = resid ? resid + ((size_t)b * Co + co) * LLv + tn : nullptr;
#pragma unroll
            for (int nj = 0; nj < 8; ++nj) {
                int col = wn * 64 + nj * 8 + (lane & 3) * 2;
                float2 o;
                o.x = acc[mi][nj][h * 2 + 0] * scv + shv;
                o.y = acc[mi][nj][h * 2 + 1] * scv + shv;
                if (rp) {
                    float2 rv = *(const float2*)(rp + col);
                    o.x += rv.x; o.y += rv.y;
                }
                *(float2*)(op + col) = o;
            }
        }
    }
}

// -------------------- M = k^T v per (b,h) ----------------------------------
__global__ void __launch_bounds__(256) kv_outer_k(
    const float* __restrict__ sk, const float* __restrict__ sv, float* __restrict__ M) {
    int bh = blockIdx.x;
    int b = bh >> 3, h = bh & 7;
    size_t off = ((size_t)b * CC + (size_t)h * HD) * LLv;
    const float* K = sk + off;
    const float* V = sv + off;
    __shared__ float Ks[64][65];
    __shared__ float Vs[64][65];
    float acc[4][4];
#pragma unroll
    for (int i = 0; i < 4; ++i)
#pragma unroll
        for (int j = 0; j < 4; ++j) acc[i][j] = 0.f;
    int tr = threadIdx.x >> 4, tc = threadIdx.x & 15;
    int row = threadIdx.x >> 2, cb = (threadIdx.x & 3) * 16;
    for (int l0 = 0; l0 < LLv; l0 += 64) {
        __syncthreads();
#pragma unroll
        for (int u = 0; u < 16; u += 4) {
            float4 kv = *(const float4*)&K[(size_t)row * LLv + l0 + cb + u];
            Ks[row][cb + u] = kv.x; Ks[row][cb + u + 1] = kv.y;
            Ks[row][cb + u + 2] = kv.z; Ks[row][cb + u + 3] = kv.w;
            float4 vv = *(const float4*)&V[(size_t)row * LLv + l0 + cb + u];
            Vs[row][cb + u] = vv.x; Vs[row][cb + u + 1] = vv.y;
            Vs[row][cb + u + 2] = vv.z; Vs[row][cb + u + 3] = vv.w;
        }
        __syncthreads();
#pragma unroll
        for (int ll = 0; ll < 64; ++ll) {
            float a[4], c[4];
#pragma unroll
            for (int i = 0; i < 4; ++i) a[i] = Ks[tr * 4 + i][ll];
#pragma unroll
            for (int i = 0; i < 4; ++i) c[i] = Vs[tc * 4 + i][ll];
#pragma unroll
            for (int i = 0; i < 4; ++i)
#pragma unroll
                for (int j = 0; j < 4; ++j) acc[i][j] += a[i] * c[j];
        }
    }
#pragma unroll
    for (int i = 0; i < 4; ++i)
#pragma unroll
        for (int j = 0; j < 4; ++j)
            M[((size_t)bh * HD + tr * 4 + i) * HD + tc * 4 + j] = acc[i][j];
}

// -------------------- o = q @ M -> spike -> soT fp16 [B,L,C] ----------------
__global__ void __launch_bounds__(256) qm_spike_k(
    const float* __restrict__ sq, const float* __restrict__ M, __half* __restrict__ soT) {
    int bh = blockIdx.y;
    int b = bh >> 3, h = bh & 7;
    int l = blockIdx.x * 256 + threadIdx.x;
    __shared__ float Ms[HD * HD];
#pragma unroll
    for (int u = 0; u < 16; ++u)
        Ms[u * 256 + threadIdx.x] = M[(size_t)bh * HD * HD + u * 256 + threadIdx.x];
    __syncthreads();
    size_t off = ((size_t)b * CC + (size_t)h * HD) * LLv + l;
    const float* Q = sq + off;
    float acc[HD];
#pragma unroll
    for (int jp = 0; jp < HD; ++jp) acc[jp] = 0.f;
    for (int j = 0; j < HD; ++j) {
        float qv = Q[(size_t)j * LLv];
#pragma unroll
        for (int jp = 0; jp < HD; ++jp) acc[jp] += qv * Ms[j * HD + jp];
    }
    __half* O = soT + ((size_t)b * LLv + l) * CC + h * HD;
#pragma unroll
    for (int jp = 0; jp < HD; ++jp) {
        float o = acc[jp] * 0.125f;
        O[jp] = __float2half_rn(((o / 1.5f - 1.f) >= 0.f) ? 1.f : 0.f);
    }
}

// ---------------------------------------------------------------------------
extern "C" void kernel_launch(void* const* d_in, const int* in_sizes, int n_in,
                              void* d_out, int out_size) {
    const float* x       = (const float*)d_in[0];
    const float* attn_bn = (const float*)d_in[1];
    const float* q_w     = (const float*)d_in[2];
    const float* q_bn    = (const float*)d_in[3];
    const float* k_w     = (const float*)d_in[4];
    const float* k_bn    = (const float*)d_in[5];
    const float* v_w     = (const float*)d_in[6];
    const float* v_bn    = (const float*)d_in[7];
    const float* proj_w  = (const float*)d_in[8];
    const float* proj_b  = (const float*)d_in[9];
    const float* mlp_bn  = (const float*)d_in[10];
    const float* fc1_w   = (const float*)d_in[11];
    const float* fc1_b   = (const float*)d_in[12];
    const float* fc1_bn  = (const float*)d_in[13];
    const float* fc2_w   = (const float*)d_in[14];
    const float* fc2_b   = (const float*)d_in[15];
    float* out = (float*)d_out;

    float *y, *sq, *sk, *sv, *x1, *M, *scale, *shift;
    __half *xqT, *soT, *s2T, *w;
    cudaGetSymbolAddress((void**)&y,   g_y);
    cudaGetSymbolAddress((void**)&sq,  g_sq);
    cudaGetSymbolAddress((void**)&sk,  g_sk);
    cudaGetSymbolAddress((void**)&sv,  g_sv);
    cudaGetSymbolAddress((void**)&x1,  g_x1);
    cudaGetSymbolAddress((void**)&M,   g_M);
    cudaGetSymbolAddress((void**)&scale, g_scale);
    cudaGetSymbolAddress((void**)&shift, g_shift);
    cudaGetSymbolAddress((void**)&xqT, g_xqT);
    cudaGetSymbolAddress((void**)&soT, g_soT);
    cudaGetSymbolAddress((void**)&s2T, g_s2T);
    cudaGetSymbolAddress((void**)&w,   g_w);

    cudaFuncSetAttribute(gemm_mma_k, cudaFuncAttributeMaxDynamicSharedMemorySize, DYN_SMEM);

    const int SZ = CC * CC;          // 262144
    const int SZH = HIDN * CC;       // 1048576
    __half* wq  = w;
    __half* wk  = w + 2 * (size_t)SZ;
    __half* wv  = w + 4 * (size_t)SZ;
    __half* wp  = w + 6 * (size_t)SZ;
    __half* wf1 = w + 8 * (size_t)SZ;
    __half* wf2 = wf1 + 2 * (size_t)SZH;

    bnprep_k<<<2, 256>>>(attn_bn, nullptr, scale + 0 * 2048, shift + 0 * 2048, CC);
    bnprep_k<<<2, 256>>>(q_bn,    nullptr, scale + 1 * 2048, shift + 1 * 2048, CC);
    bnprep_k<<<2, 256>>>(k_bn,    nullptr, scale + 2 * 2048, shift + 2 * 2048, CC);
    bnprep_k<<<2, 256>>>(v_bn,    nullptr, scale + 3 * 2048, shift + 3 * 2048, CC);
    bnprep_k<<<2, 256>>>(mlp_bn,  nullptr, scale + 4 * 2048, shift + 4 * 2048, CC);
    bnprep_k<<<8, 256>>>(fc1_bn,  fc1_b,   scale + 5 * 2048, shift + 5 * 2048, HIDN);

    wsplit_k<<<SZ / 256, 256>>>(q_w, wq, SZ);
    wsplit_k<<<SZ / 256, 256>>>(k_w, wk, SZ);
    wsplit_k<<<SZ / 256, 256>>>(v_w, wv, SZ);
    wsplit_k<<<SZ / 256, 256>>>(proj_w, wp, SZ);
    wsplit_k<<<SZH / 256, 256>>>(fc1_w, wf1, SZH);
    wsplit_k<<<SZH / 256, 256>>>(fc2_w, wf2, SZH);

    dim3 ltr(32, 8);
    dim3 gtr512(16, 16, BB);
    dim3 gtr2048(16, 64, BB);
    dim3 gg512(LLv / NT, CC / MT, BB);     // (8,4,4) = 128 CTAs
    dim3 gg2048(LLv / NT, HIDN / MT, BB);  // (8,16,4) = 512 CTAs

    // attn input spikes (BN_attn + LIF) -> xqT fp16 [B,L,C]
    lif_tr_k<<<gtr512, ltr>>>(x, xqT, scale + 0 * 2048, shift + 0 * 2048, CC);

    // q/k/v
    gemm_mma_k<<<gg512, 256, DYN_SMEM>>>(wq, xqT, y, scale + 1 * 2048, shift + 1 * 2048, nullptr, CC, CC);
    lif_t_k<<<4096, 256>>>(y, sq, CC);
    gemm_mma_k<<<gg512, 256, DYN_SMEM>>>(wk, xqT, y, scale + 2 * 2048, shift + 2 * 2048, nullptr, CC, CC);
    lif_t_k<<<4096, 256>>>(y, sk, CC);
    gemm_mma_k<<<gg512, 256, DYN_SMEM>>>(wv, xqT, y, scale + 3 * 2048, shift + 3 * 2048, nullptr, CC, CC);
    lif_t_k<<<4096, 256>>>(y, sv, CC);

    // attention: exact q (k^T v)
    kv_outer_k<<<32, 256>>>(sk, sv, M);
    qm_spike_k<<<dim3(8, 32), 256>>>(sq, M, soT);

    // proj + residual
    gemm_mma_k<<<gg512, 256, DYN_SMEM>>>(wp, soT, x1, nullptr, proj_b, x, CC, CC);

    // MLP
    lif_tr_k<<<gtr512, ltr>>>(x1, xqT, scale + 4 * 2048, shift + 4 * 2048, CC);
    gemm_mma_k<<<gg2048, 256, DYN_SMEM>>>(wf1, xqT, y, scale + 5 * 2048, shift + 5 * 2048, nullptr, HIDN, CC);
    lif_tr_k<<<gtr2048, ltr>>>(y, s2T, nullptr, nullptr, HIDN);
    gemm_mma_k<<<gg512, 256, DYN_SMEM>>>(wf2, s2T, out, nullptr, fc2_b, x1, CC, HIDN);
}

// round 8
// speedup vs baseline: 3.9088x; 1.0837x over previous
#include <cuda_runtime.h>
#include <cuda_fp16.h>
#include <cstdint>
#include <cstddef>

// ---------------------------------------------------------------------------
// SpikingTransformerBlock, mma.sync fp16 2-term path (base sm_100 compatible)
// B=4, C=512, T=4, N=512, L=2048, HID=2048, H=8, d=64
// R8 (= R7 resubmit): merged prologue (2 launches), fused qkv GEMM (Co=1536)
// with BN+LIF epilogue via t-major columns; 11 launches total.
// ---------------------------------------------------------------------------

#define BB 4
#define CC 512
#define TT 4
#define NNv 512
#define LLv 2048
#define HIDN 2048
#define NH 8
#define HD 64
#define CQKV 1536

#define MT 128
#define NT 256
#define KCH 64
#define TERMS 2
#define A_TERM_BYTES (MT * KCH * 2)           // 16384
#define A_BYTES (TERMS * A_TERM_BYTES)        // 32768
#define B_BYTES (NT * KCH * 2)                // 32768
#define STAGE_BYTES (A_BYTES + B_BYTES)       // 65536
#define NSTAGE 3
#define DYN_SMEM (NSTAGE * STAGE_BYTES)       // 196608

#define SW(o) ((o) ^ (((o) >> 3) & 0x70))

#define SZ   (CC * CC)      // 262144
#define SZH  (HIDN * CC)    // 1048576

// -------------------- device scratch ---------------------------------------
__device__ float g_y  [(size_t)BB * HIDN * LLv];     // fc1 pre-LIF out
__device__ float g_skv[(size_t)BB * CQKV * LLv];     // qkv spikes fp32 [B,1536,L]
__device__ float g_x1 [(size_t)BB * CC * LLv];
__device__ float g_M  [(size_t)BB * NH * HD * HD];
__device__ __half g_xqT[(size_t)BB * LLv * CC];
__device__ __half g_soT[(size_t)BB * LLv * CC];
__device__ __half g_s2T[(size_t)BB * LLv * HIDN];
__device__ __half g_w[8 * SZ + 4 * SZH];             // wqkv | wp | wf1 | wf2
__device__ float g_scale[6 * 2048];
__device__ float g_shift[6 * 2048];

// -------------------- helpers ----------------------------------------------
__device__ __forceinline__ uint32_t smem_u32(const void* p) {
    uint32_t a;
    asm("{ .reg .u64 t; cvta.to.shared.u64 t, %1; cvt.u32.u64 %0, t; }" : "=r"(a) : "l"(p));
    return a;
}
#define CP16(sa, gp) \
    asm volatile("cp.async.cg.shared.global [%0], [%1], 16;" :: "r"(sa), "l"(gp) : "memory")
#define CP_COMMIT() asm volatile("cp.async.commit_group;" ::: "memory")
#define CP_WAIT1() asm volatile("cp.async.wait_group 1;" ::: "memory")
#define CP_WAIT0() asm volatile("cp.async.wait_group 0;" ::: "memory")

__device__ __forceinline__ void ldm_x4(uint32_t& r0, uint32_t& r1, uint32_t& r2, uint32_t& r3,
                                       uint32_t addr) {
    asm volatile("ldmatrix.sync.aligned.m8n8.x4.shared.b16 {%0,%1,%2,%3}, [%4];"
                 : "=r"(r0), "=r"(r1), "=r"(r2), "=r"(r3) : "r"(addr));
}
__device__ __forceinline__ void mma16816(float* c, uint32_t a0, uint32_t a1, uint32_t a2,
                                         uint32_t a3, uint32_t b0, uint32_t b1) {
    asm volatile("mma.sync.aligned.m16n8k16.row.col.f32.f16.f16.f32 "
                 "{%0,%1,%2,%3},{%4,%5,%6,%7},{%8,%9},{%0,%1,%2,%3};"
                 : "+f"(c[0]), "+f"(c[1]), "+f"(c[2]), "+f"(c[3])
                 : "r"(a0), "r"(a1), "r"(a2), "r"(a3), "r"(b0), "r"(b1));
}

// -------------------- merged BN fold (all 6 BNs, 1 launch) ------------------
// slots: 0=attn 1=q 2=k 3=v 4=mlp (C=512), 5=fc1 (C=2048, +fc1 bias folded)
__global__ void bnprep_all(const float* __restrict__ p0, const float* __restrict__ p1,
                           const float* __restrict__ p2, const float* __restrict__ p3,
                           const float* __restrict__ p4, const float* __restrict__ p5,
                           const float* __restrict__ fc1b,
                           float* __restrict__ scale, float* __restrict__ shift) {
    int slot = blockIdx.y;
    int Cdim = (slot == 5) ? 2048 : 512;
    int c = blockIdx.x * 256 + threadIdx.x;
    if (c >= Cdim) return;
    const float* p = (slot == 0) ? p0 : (slot == 1) ? p1 : (slot == 2) ? p2 :
                     (slot == 3) ? p3 : (slot == 4) ? p4 : p5;
    float g = p[c], be = p[Cdim + c], m = p[2 * Cdim + c], va = p[3 * Cdim + c];
    float inv = g / sqrtf(va + 1e-5f);
    float sh = be - m * inv;
    if (slot == 5) sh += fc1b[c] * inv;
    scale[slot * 2048 + c] = inv;
    shift[slot * 2048 + c] = sh;
}

// -------------------- merged weight split (all 6 weights, 1 launch) ---------
// wqkv: [2][1536][512] (term stride 3*SZ); wp: [2][512][512]; wf1/wf2: [2][...]
__global__ void wsplit_all(const float* __restrict__ qw, const float* __restrict__ kw,
                           const float* __restrict__ vw, const float* __restrict__ pw,
                           const float* __restrict__ f1, const float* __restrict__ f2,
                           __half* __restrict__ wqkv, __half* __restrict__ wp,
                           __half* __restrict__ wf1, __half* __restrict__ wf2) {
    int i = blockIdx.x * 256 + threadIdx.x;
    const float* src; __half *dhi, *dlo;
    if (i < 3 * SZ) {
        int seg = i / SZ, j = i - seg * SZ;
        src = (seg == 0) ? qw + j : (seg == 1) ? kw + j : vw + j;
        dhi = wqkv + seg * SZ + j; dlo = wqkv + 3 * SZ + seg * SZ + j;
    } else if (i < 4 * SZ) {
        int j = i - 3 * SZ;
        src = pw + j; dhi = wp + j; dlo = wp + SZ + j;
    } else if (i < 4 * SZ + SZH) {
        int j = i - 4 * SZ;
        src = f1 + j; dhi = wf1 + j; dlo = wf1 + SZH + j;
    } else {
        int j = i - 4 * SZ - SZH;
        if (j >= SZH) return;
        src = f2 + j; dhi = wf2 + j; dlo = wf2 + SZH + j;
    }
    float x = *src;
    __half h = __float2half_rn(x);
    *dhi = h;
    *dlo = __float2half_rn(x - __half2float(h));
}

// -------------------- LIF (+opt BN) -> transposed fp16 spikes ---------------
__global__ void lif_tr_k(const float* __restrict__ in, __half* __restrict__ outT,
                         const float* __restrict__ scale, const float* __restrict__ shift,
                         int Cdim) {
    __shared__ float tile[TT][32][33];
    int b = blockIdx.z, c0 = blockIdx.y * 32, n0 = blockIdx.x * 32;
    int tx = threadIdx.x, ty = threadIdx.y;
#pragma unroll
    for (int i = 0; i < 4; ++i) {
        int c = c0 + ty + 8 * i;
        float sc = scale ? scale[c] : 1.f;
        float sh = shift ? shift[c] : 0.f;
        size_t base = ((size_t)b * Cdim + c) * LLv + n0 + tx;
        float v = 0.f;
#pragma unroll
        for (int t = 0; t < TT; ++t) {
            float xv = in[base + (size_t)t * NNv] * sc + sh;
            v += (xv - v) / 1.5f;
            float sp = (v >= 1.f) ? 1.f : 0.f;
            tile[t][ty + 8 * i][tx] = sp;
            v = (v >= 1.f) ? 0.f : v;
        }
    }
    __syncthreads();
#pragma unroll
    for (int t = 0; t < TT; ++t)
#pragma unroll
        for (int i = 0; i < 4; ++i) {
            int l = t * NNv + n0 + ty + 8 * i;
            outT[((size_t)b * LLv + l) * Cdim + c0 + tx] =
                __float2half_rn(tile[t][tx][ty + 8 * i]);
        }
}

// -------------------- fused qkv GEMM + BN + LIF -----------------------------
// out spikes fp32 [B,1536,L]; W [2][1536][512]; BT [B,L,512] fp16.
// Columns are t-major: B-tile row ridx = t*64+nloc -> l = t*512 + n0 + nloc,
// so each thread holds all 4 timesteps of its (co, n) pairs -> LIF in regs.
__global__ void __launch_bounds__(256, 1) gemm_qkv_k(
    const __half* __restrict__ Wspl, const __half* __restrict__ BT,
    float* __restrict__ out, const float* __restrict__ scale,
    const float* __restrict__ shift) {

    extern __shared__ __align__(16) char smem[];
    uint32_t sb = smem_u32(smem);
    int tid = threadIdx.x;
    int lane = tid & 31, w = tid >> 5;
    int wm = w & 1, wn = w >> 1;

    int b = blockIdx.z;
    int tm = blockIdx.y * MT;
    int n0 = blockIdx.x * 64;
    const __half* Bt = BT + (size_t)b * LLv * CC;
    const size_t termstride = (size_t)CQKV * CC;
    const int KC = CC / KCH;   // 8

    float acc[4][8][4];
#pragma unroll
    for (int i = 0; i < 4; ++i)
#pragma unroll
        for (int j = 0; j < 8; ++j)
#pragma unroll
            for (int r = 0; r < 4; ++r) acc[i][j][r] = 0.f;

    auto issue_loads = [&](int c) {
        uint32_t base = sb + (uint32_t)(c % NSTAGE) * STAGE_BYTES;
        int k0 = c * KCH;
#pragma unroll
        for (int i = 0; i < 8; ++i) {                    // A
            int idx = i * 256 + tid;
            int term = idx >> 10;
            int within = idx & 1023;
            int row = within >> 3, c16 = within & 7;
            uint32_t o = (uint32_t)(row * 128 + c16 * 16);
            CP16(base + term * A_TERM_BYTES + SW(o),
                 Wspl + (size_t)term * termstride + (size_t)(tm + row) * CC + k0 + c16 * 8);
        }
#pragma unroll
        for (int i = 0; i < 8; ++i) {                    // B, t-major rows
            int idx = i * 256 + tid;
            int ridx = idx >> 3, c16 = idx & 7;
            int t = ridx >> 6, nloc = ridx & 63;
            int l = t * NNv + n0 + nloc;
            uint32_t o = (uint32_t)(ridx * 128 + c16 * 16);
            CP16(base + A_BYTES + SW(o),
                 Bt + (size_t)l * CC + k0 + c16 * 8);
        }
        CP_COMMIT();
    };

    issue_loads(0);
    issue_loads(1);

    int sub = lane >> 3;
    int lrow = lane & 7;

    for (int c = 0; c < KC; ++c) {
        uint32_t base = sb + (uint32_t)(c % NSTAGE) * STAGE_BYTES;
        if (c < KC - 1) CP_WAIT1(); else CP_WAIT0();
        __syncthreads();
        if (c + 2 < KC) issue_loads(c + 2);

        uint32_t abase = base;
        uint32_t bbase = base + A_BYTES;
#pragma unroll
        for (int ks = 0; ks < 4; ++ks) {
            uint32_t bfr[4][4];
#pragma unroll
            for (int t = 0; t < 4; ++t) {
                int rbase = t * 64 + wn * 16 + (sub >> 1) * 8 + lrow;
                uint32_t o = (uint32_t)(rbase * 128 + ks * 32 + (sub & 1) * 16);
                ldm_x4(bfr[t][0], bfr[t][1], bfr[t][2], bfr[t][3], bbase + SW(o));
            }
#pragma unroll
            for (int term = 0; term < TERMS; ++term) {
                uint32_t tb = abase + term * A_TERM_BYTES;
                uint32_t af[4][4];
#pragma unroll
                for (int mi = 0; mi < 4; ++mi) {
                    int m = wm * 64 + mi * 16 + (sub & 1) * 8 + lrow;
                    uint32_t o = (uint32_t)(m * 128 + ks * 32 + (sub >> 1) * 16);
                    ldm_x4(af[mi][0], af[mi][1], af[mi][2], af[mi][3], tb + SW(o));
                }
#pragma unroll
                for (int mi = 0; mi < 4; ++mi)
#pragma unroll
                    for (int nj = 0; nj < 8; ++nj)
                        mma16816(acc[mi][nj], af[mi][0], af[mi][1], af[mi][2], af[mi][3],
                                 bfr[nj >> 1][(nj & 1) * 2],
                                 bfr[nj >> 1][(nj & 1) * 2 + 1]);
            }
        }
    }

    // epilogue: BN + LIF over t (nj = t*2 + uh), write spikes fp32
#pragma unroll
    for (int mi = 0; mi < 4; ++mi) {
#pragma unroll
        for (int h = 0; h < 2; ++h) {
            int co = tm + wm * 64 + mi * 16 + h * 8 + (lane >> 2);
            int sidx = ((co >> 9) << 11) | (co & 511);   // slots q/k/v are 2048 apart
            float scv = scale[sidx], shv = shift[sidx];
            float* op = out + ((size_t)b * CQKV + co) * LLv;
#pragma unroll
            for (int uh = 0; uh < 2; ++uh) {
                float v0 = 0.f, v1 = 0.f;
#pragma unroll
                for (int t = 0; t < 4; ++t) {
                    int nj = t * 2 + uh;
                    float x0 = acc[mi][nj][h * 2 + 0] * scv + shv;
                    float x1 = acc[mi][nj][h * 2 + 1] * scv + shv;
                    v0 += (x0 - v0) / 1.5f;
                    float s0 = (v0 >= 1.f) ? 1.f : 0.f; v0 = (v0 >= 1.f) ? 0.f : v0;
                    v1 += (x1 - v1) / 1.5f;
                    float s1 = (v1 >= 1.f) ? 1.f : 0.f; v1 = (v1 >= 1.f) ? 0.f : v1;
                    int l = t * NNv + n0 + wn * 16 + uh * 8 + (lane & 3) * 2;
                    float2 o2; o2.x = s0; o2.y = s1;
                    *(float2*)(op + l) = o2;
                }
            }
        }
    }
}

// -------------------- plain mma GEMM (proj/fc1/fc2) -------------------------
__global__ void __launch_bounds__(256, 1) gemm_mma_k(
    const __half* __restrict__ Wspl, const __half* __restrict__ BT,
    float* __restrict__ out, const float* __restrict__ scale, const float* __restrict__ shift,
    const float* __restrict__ resid, int Co, int Ci) {

    extern __shared__ __align__(16) char smem[];
    uint32_t sb = smem_u32(smem);
    int tid = threadIdx.x;
    int lane = tid & 31, w = tid >> 5;
    int wm = w & 1, wn = w >> 1;

    int b = blockIdx.z;
    int tm = blockIdx.y * MT;
    int tn = blockIdx.x * NT;
    const __half* Bt = BT + (size_t)b * LLv * Ci;
    const size_t termstride = (size_t)Co * Ci;
    const int KC = Ci / KCH;

    float acc[4][8][4];
#pragma unroll
    for (int i = 0; i < 4; ++i)
#pragma unroll
        for (int j = 0; j < 8; ++j)
#pragma unroll
            for (int r = 0; r < 4; ++r) acc[i][j][r] = 0.f;

    auto issue_loads = [&](int c) {
        uint32_t base = sb + (uint32_t)(c % NSTAGE) * STAGE_BYTES;
        int k0 = c * KCH;
#pragma unroll
        for (int i = 0; i < 8; ++i) {
            int idx = i * 256 + tid;
            int term = idx >> 10;
            int within = idx & 1023;
            int row = within >> 3, c16 = within & 7;
            uint32_t o = (uint32_t)(row * 128 + c16 * 16);
            CP16(base + term * A_TERM_BYTES + SW(o),
                 Wspl + (size_t)term * termstride + (size_t)(tm + row) * Ci + k0 + c16 * 8);
        }
#pragma unroll
        for (int i = 0; i < 8; ++i) {
            int idx = i * 256 + tid;
            int row = idx >> 3, c16 = idx & 7;
            uint32_t o = (uint32_t)(row * 128 + c16 * 16);
            CP16(base + A_BYTES + SW(o),
                 Bt + (size_t)(tn + row) * Ci + k0 + c16 * 8);
        }
        CP_COMMIT();
    };

    issue_loads(0);
    issue_loads(1);

    int sub = lane >> 3;
    int lrow = lane & 7;

    for (int c = 0; c < KC; ++c) {
        uint32_t base = sb + (uint32_t)(c % NSTAGE) * STAGE_BYTES;
        if (c < KC - 1) CP_WAIT1(); else CP_WAIT0();
        __syncthreads();
        if (c + 2 < KC) issue_loads(c + 2);

        uint32_t abase = base;
        uint32_t bbase = base + A_BYTES;
#pragma unroll
        for (int ks = 0; ks < 4; ++ks) {
            uint32_t bfr[4][4];
#pragma unroll
            for (int ni = 0; ni < 4; ++ni) {
                int n = wn * 64 + ni * 16 + (sub >> 1) * 8 + lrow;
                uint32_t o = (uint32_t)(n * 128 + ks * 32 + (sub & 1) * 16);
                ldm_x4(bfr[ni][0], bfr[ni][1], bfr[ni][2], bfr[ni][3], bbase + SW(o));
            }
#pragma unroll
            for (int term = 0; term < TERMS; ++term) {
                uint32_t tb = abase + term * A_TERM_BYTES;
                uint32_t af[4][4];
#pragma unroll
                for (int mi = 0; mi < 4; ++mi) {
                    int m = wm * 64 + mi * 16 + (sub & 1) * 8 + lrow;
                    uint32_t o = (uint32_t)(m * 128 + ks * 32 + (sub >> 1) * 16);
                    ldm_x4(af[mi][0], af[mi][1], af[mi][2], af[mi][3], tb + SW(o));
                }
#pragma unroll
                for (int mi = 0; mi < 4; ++mi)
#pragma unroll
                    for (int nj = 0; nj < 8; ++nj)
                        mma16816(acc[mi][nj], af[mi][0], af[mi][1], af[mi][2], af[mi][3],
                                 bfr[nj >> 1][(nj & 1) * 2],
                                 bfr[nj >> 1][(nj & 1) * 2 + 1]);
            }
        }
    }

#pragma unroll
    for (int mi = 0; mi < 4; ++mi) {
#pragma unroll
        for (int h = 0; h < 2; ++h) {
            int co = tm + wm * 64 + mi * 16 + h * 8 + (lane >> 2);
            float scv = scale ? scale[co] : 1.f;
            float shv = shift ? shift[co] : 0.f;
            float* op = out + ((size_t)b * Co + co) * LLv + tn;
            const float* rp = resid ? resid + ((size_t)b * Co + co) * LLv + tn : nullptr;
#pragma unroll
            for (int nj = 0; nj < 8; ++nj) {
                int col = wn * 64 + nj * 8 + (lane & 3) * 2;
                float2 o;
                o.x = acc[mi][nj][h * 2 + 0] * scv + shv;
                o.y = acc[mi][nj][h * 2 + 1] * scv + shv;
                if (rp) {
                    float2 rv = *(const float2*)(rp + col);
                    o.x += rv.x; o.y += rv.y;
                }
                *(float2*)(op + col) = o;
            }
        }
    }
}

// -------------------- M = k^T v per (b,h), from skv -------------------------
__global__ void __launch_bounds__(256) kv_outer_k(
    const float* __restrict__ skv, float* __restrict__ M) {
    int bh = blockIdx.x;
    int b = bh >> 3, h = bh & 7;
    const float* K = skv + ((size_t)b * CQKV + 512 + h * HD) * LLv;
    const float* V = skv + ((size_t)b * CQKV + 1024 + h * HD) * LLv;
    __shared__ float Ks[64][65];
    __shared__ float Vs[64][65];
    float acc[4][4];
#pragma unroll
    for (int i = 0; i < 4; ++i)
#pragma unroll
        for (int j = 0; j < 4; ++j) acc[i][j] = 0.f;
    int tr = threadIdx.x >> 4, tc = threadIdx.x & 15;
    int row = threadIdx.x >> 2, cb = (threadIdx.x & 3) * 16;
    for (int l0 = 0; l0 < LLv; l0 += 64) {
        __syncthreads();
#pragma unroll
        for (int u = 0; u < 16; u += 4) {
            float4 kv = *(const float4*)&K[(size_t)row * LLv + l0 + cb + u];
            Ks[row][cb + u] = kv.x; Ks[row][cb + u + 1] = kv.y;
            Ks[row][cb + u + 2] = kv.z; Ks[row][cb + u + 3] = kv.w;
            float4 vv = *(const float4*)&V[(size_t)row * LLv + l0 + cb + u];
            Vs[row][cb + u] = vv.x; Vs[row][cb + u + 1] = vv.y;
            Vs[row][cb + u + 2] = vv.z; Vs[row][cb + u + 3] = vv.w;
        }
        __syncthreads();
#pragma unroll
        for (int ll = 0; ll < 64; ++ll) {
            float a[4], c[4];
#pragma unroll
            for (int i = 0; i < 4; ++i) a[i] = Ks[tr * 4 + i][ll];
#pragma unroll
            for (int i = 0; i < 4; ++i) c[i] = Vs[tc * 4 + i][ll];
#pragma unroll
            for (int i = 0; i < 4; ++i)
#pragma unroll
                for (int j = 0; j < 4; ++j) acc[i][j] += a[i] * c[j];
        }
    }
#pragma unroll
    for (int i = 0; i < 4; ++i)
#pragma unroll
        for (int j = 0; j < 4; ++j)
            M[((size_t)bh * HD + tr * 4 + i) * HD + tc * 4 + j] = acc[i][j];
}

// -------------------- o = q @ M -> spike -> soT fp16 [B,L,C] ----------------
__global__ void __launch_bounds__(256) qm_spike_k(
    const float* __restrict__ skv, const float* __restrict__ M, __half* __restrict__ soT) {
    int bh = blockIdx.y;
    int b = bh >> 3, h = bh & 7;
    int l = blockIdx.x * 256 + threadIdx.x;
    __shared__ float Ms[HD * HD];
#pragma unroll
    for (int u = 0; u < 16; ++u)
        Ms[u * 256 + threadIdx.x] = M[(size_t)bh * HD * HD + u * 256 + threadIdx.x];
    __syncthreads();
    const float* Q = skv + ((size_t)b * CQKV + h * HD) * LLv + l;
    float acc[HD];
#pragma unroll
    for (int jp = 0; jp < HD; ++jp) acc[jp] = 0.f;
    for (int j = 0; j < HD; ++j) {
        float qv = Q[(size_t)j * LLv];
#pragma unroll
        for (int jp = 0; jp < HD; ++jp) acc[jp] += qv * Ms[j * HD + jp];
    }
    __half* O = soT + ((size_t)b * LLv + l) * CC + h * HD;
#pragma unroll
    for (int jp = 0; jp < HD; ++jp) {
        float o = acc[jp] * 0.125f;
        O[jp] = __float2half_rn(((o / 1.5f - 1.f) >= 0.f) ? 1.f : 0.f);
    }
}

// ---------------------------------------------------------------------------
extern "C" void kernel_launch(void* const* d_in, const int* in_sizes, int n_in,
                              void* d_out, int out_size) {
    const float* x       = (const float*)d_in[0];
    const float* attn_bn = (const float*)d_in[1];
    const float* q_w     = (const float*)d_in[2];
    const float* q_bn    = (const float*)d_in[3];
    const float* k_w     = (const float*)d_in[4];
    const float* k_bn    = (const float*)d_in[5];
    const float* v_w     = (const float*)d_in[6];
    const float* v_bn    = (const float*)d_in[7];
    const float* proj_w  = (const float*)d_in[8];
    const float* proj_b  = (const float*)d_in[9];
    const float* mlp_bn  = (const float*)d_in[10];
    const float* fc1_w   = (const float*)d_in[11];
    const float* fc1_b   = (const float*)d_in[12];
    const float* fc1_bn  = (const float*)d_in[13];
    const float* fc2_w   = (const float*)d_in[14];
    const float* fc2_b   = (const float*)d_in[15];
    float* out = (float*)d_out;

    float *y, *skv, *x1, *M, *scale, *shift;
    __half *xqT, *soT, *s2T, *w;
    cudaGetSymbolAddress((void**)&y,   g_y);
    cudaGetSymbolAddress((void**)&skv, g_skv);
    cudaGetSymbolAddress((void**)&x1,  g_x1);
    cudaGetSymbolAddress((void**)&M,   g_M);
    cudaGetSymbolAddress((void**)&scale, g_scale);
    cudaGetSymbolAddress((void**)&shift, g_shift);
    cudaGetSymbolAddress((void**)&xqT, g_xqT);
    cudaGetSymbolAddress((void**)&soT, g_soT);
    cudaGetSymbolAddress((void**)&s2T, g_s2T);
    cudaGetSymbolAddress((void**)&w,   g_w);

    cudaFuncSetAttribute(gemm_mma_k, cudaFuncAttributeMaxDynamicSharedMemorySize, DYN_SMEM);
    cudaFuncSetAttribute(gemm_qkv_k, cudaFuncAttributeMaxDynamicSharedMemorySize, DYN_SMEM);

    __half* wqkv = w;                       // [2][1536][512]
    __half* wp   = w + 6 * (size_t)SZ;      // [2][512][512]
    __half* wf1  = w + 8 * (size_t)SZ;      // [2][2048][512]
    __half* wf2  = wf1 + 2 * (size_t)SZH;   // [2][512][2048]

    // merged prologue (2 launches)
    bnprep_all<<<dim3(8, 6), 256>>>(attn_bn, q_bn, k_bn, v_bn, mlp_bn, fc1_bn, fc1_b,
                                    scale, shift);
    wsplit_all<<<(4 * SZ + 2 * SZH) / 256, 256>>>(q_w, k_w, v_w, proj_w, fc1_w, fc2_w,
                                                  wqkv, wp, wf1, wf2);

    dim3 ltr(32, 8);
    dim3 gtr512(16, 16, BB);
    dim3 gtr2048(16, 64, BB);
    dim3 gg512(LLv / NT, CC / MT, BB);      // (8,4,4)

    // attn input spikes (BN_attn + LIF) -> xqT fp16 [B,L,C]
    lif_tr_k<<<gtr512, ltr>>>(x, xqT, scale, shift, CC);

    // fused q/k/v GEMM + BN + LIF -> skv spikes fp32 [B,1536,L]
    gemm_qkv_k<<<dim3(8, 12, 4), 256, DYN_SMEM>>>(wqkv, xqT, skv,
                                                  scale + 2048, shift + 2048);

    // attention: exact q (k^T v)
    kv_outer_k<<<32, 256>>>(skv, M);
    qm_spike_k<<<dim3(8, 32), 256>>>(skv, M, soT);

    // proj + residual -> x1
    gemm_mma_k<<<gg512, 256, DYN_SMEM>>>(wp, soT, x1, nullptr, proj_b, x, CC, CC);

    // MLP
    lif_tr_k<<<gtr512, ltr>>>(x1, xqT, scale + 4 * 2048, shift + 4 * 2048, CC);
    gemm_mma_k<<<dim3(8, 16, 4), 256, DYN_SMEM>>>(wf1, xqT, y,
                                                  scale + 5 * 2048, shift + 5 * 2048,
                                                  nullptr, HIDN, CC);
    lif_tr_k<<<gtr2048, ltr>>>(y, s2T, nullptr, nullptr, HIDN);
    gemm_mma_k<<<gg512, 256, DYN_SMEM>>>(wf2, s2T, out, nullptr, fc2_b, x1, CC, HIDN);
}

// round 9
// speedup vs baseline: 4.4846x; 1.1473x over previous
#include <cuda_runtime.h>
#include <cuda_fp16.h>
#include <cstdint>
#include <cstddef>

// ---------------------------------------------------------------------------
// SpikingTransformerBlock, mma.sync fp16 2-term path (base sm_100 compatible)
// R9: split-L kv_outer (512 CTAs, exact partial sums) + fc1 GEMM with fused
// BN+LIF epilogue and smem transpose (y buffer eliminated). 10 launches.
// ---------------------------------------------------------------------------

#define BB 4
#define CC 512
#define TT 4
#define NNv 512
#define LLv 2048
#define HIDN 2048
#define NH 8
#define HD 64
#define CQKV 1536
#define KVSPL 16

#define MT 128
#define NT 256
#define KCH 64
#define TERMS 2
#define A_TERM_BYTES (MT * KCH * 2)           // 16384
#define A_BYTES (TERMS * A_TERM_BYTES)        // 32768
#define B_BYTES (NT * KCH * 2)                // 32768
#define STAGE_BYTES (A_BYTES + B_BYTES)       // 65536
#define NSTAGE 3
#define DYN_SMEM (NSTAGE * STAGE_BYTES)       // 196608

#define SW(o) ((o) ^ (((o) >> 3) & 0x70))

#define SZ   (CC * CC)      // 262144
#define SZH  (HIDN * CC)    // 1048576

// -------------------- device scratch ---------------------------------------
__device__ float g_skv[(size_t)BB * CQKV * LLv];     // qkv spikes fp32 [B,1536,L]
__device__ float g_x1 [(size_t)BB * CC * LLv];
__device__ float g_Mp [(size_t)KVSPL * BB * NH * HD * HD];  // kv partials
__device__ __half g_xqT[(size_t)BB * LLv * CC];
__device__ __half g_soT[(size_t)BB * LLv * CC];
__device__ __half g_s2T[(size_t)BB * LLv * HIDN];
__device__ __half g_w[8 * SZ + 4 * SZH];             // wqkv | wp | wf1 | wf2
__device__ float g_scale[6 * 2048];
__device__ float g_shift[6 * 2048];

// -------------------- helpers ----------------------------------------------
__device__ __forceinline__ uint32_t smem_u32(const void* p) {
    uint32_t a;
    asm("{ .reg .u64 t; cvta.to.shared.u64 t, %1; cvt.u32.u64 %0, t; }" : "=r"(a) : "l"(p));
    return a;
}
#define CP16(sa, gp) \
    asm volatile("cp.async.cg.shared.global [%0], [%1], 16;" :: "r"(sa), "l"(gp) : "memory")
#define CP_COMMIT() asm volatile("cp.async.commit_group;" ::: "memory")
#define CP_WAIT1() asm volatile("cp.async.wait_group 1;" ::: "memory")
#define CP_WAIT0() asm volatile("cp.async.wait_group 0;" ::: "memory")

__device__ __forceinline__ void ldm_x4(uint32_t& r0, uint32_t& r1, uint32_t& r2, uint32_t& r3,
                                       uint32_t addr) {
    asm volatile("ldmatrix.sync.aligned.m8n8.x4.shared.b16 {%0,%1,%2,%3}, [%4];"
                 : "=r"(r0), "=r"(r1), "=r"(r2), "=r"(r3) : "r"(addr));
}
__device__ __forceinline__ void mma16816(float* c, uint32_t a0, uint32_t a1, uint32_t a2,
                                         uint32_t a3, uint32_t b0, uint32_t b1) {
    asm volatile("mma.sync.aligned.m16n8k16.row.col.f32.f16.f16.f32 "
                 "{%0,%1,%2,%3},{%4,%5,%6,%7},{%8,%9},{%0,%1,%2,%3};"
                 : "+f"(c[0]), "+f"(c[1]), "+f"(c[2]), "+f"(c[3])
                 : "r"(a0), "r"(a1), "r"(a2), "r"(a3), "r"(b0), "r"(b1));
}

// -------------------- merged BN fold ----------------------------------------
__global__ void bnprep_all(const float* __restrict__ p0, const float* __restrict__ p1,
                           const float* __restrict__ p2, const float* __restrict__ p3,
                           const float* __restrict__ p4, const float* __restrict__ p5,
                           const float* __restrict__ fc1b,
                           float* __restrict__ scale, float* __restrict__ shift) {
    int slot = blockIdx.y;
    int Cdim = (slot == 5) ? 2048 : 512;
    int c = blockIdx.x * 256 + threadIdx.x;
    if (c >= Cdim) return;
    const float* p = (slot == 0) ? p0 : (slot == 1) ? p1 : (slot == 2) ? p2 :
                     (slot == 3) ? p3 : (slot == 4) ? p4 : p5;
    float g = p[c], be = p[Cdim + c], m = p[2 * Cdim + c], va = p[3 * Cdim + c];
    float inv = g / sqrtf(va + 1e-5f);
    float sh = be - m * inv;
    if (slot == 5) sh += fc1b[c] * inv;
    scale[slot * 2048 + c] = inv;
    shift[slot * 2048 + c] = sh;
}

// -------------------- merged weight split -----------------------------------
__global__ void wsplit_all(const float* __restrict__ qw, const float* __restrict__ kw,
                           const float* __restrict__ vw, const float* __restrict__ pw,
                           const float* __restrict__ f1, const float* __restrict__ f2,
                           __half* __restrict__ wqkv, __half* __restrict__ wp,
                           __half* __restrict__ wf1, __half* __restrict__ wf2) {
    int i = blockIdx.x * 256 + threadIdx.x;
    const float* src; __half *dhi, *dlo;
    if (i < 3 * SZ) {
        int seg = i / SZ, j = i - seg * SZ;
        src = (seg == 0) ? qw + j : (seg == 1) ? kw + j : vw + j;
        dhi = wqkv + seg * SZ + j; dlo = wqkv + 3 * SZ + seg * SZ + j;
    } else if (i < 4 * SZ) {
        int j = i - 3 * SZ;
        src = pw + j; dhi = wp + j; dlo = wp + SZ + j;
    } else if (i < 4 * SZ + SZH) {
        int j = i - 4 * SZ;
        src = f1 + j; dhi = wf1 + j; dlo = wf1 + SZH + j;
    } else {
        int j = i - 4 * SZ - SZH;
        if (j >= SZH) return;
        src = f2 + j; dhi = wf2 + j; dlo = wf2 + SZH + j;
    }
    float x = *src;
    __half h = __float2half_rn(x);
    *dhi = h;
    *dlo = __float2half_rn(x - __half2float(h));
}

// -------------------- LIF (+opt BN) -> transposed fp16 spikes ---------------
__global__ void lif_tr_k(const float* __restrict__ in, __half* __restrict__ outT,
                         const float* __restrict__ scale, const float* __restrict__ shift,
                         int Cdim) {
    __shared__ float tile[TT][32][33];
    int b = blockIdx.z, c0 = blockIdx.y * 32, n0 = blockIdx.x * 32;
    int tx = threadIdx.x, ty = threadIdx.y;
#pragma unroll
    for (int i = 0; i < 4; ++i) {
        int c = c0 + ty + 8 * i;
        float sc = scale ? scale[c] : 1.f;
        float sh = shift ? shift[c] : 0.f;
        size_t base = ((size_t)b * Cdim + c) * LLv + n0 + tx;
        float v = 0.f;
#pragma unroll
        for (int t = 0; t < TT; ++t) {
            float xv = in[base + (size_t)t * NNv] * sc + sh;
            v += (xv - v) / 1.5f;
            float sp = (v >= 1.f) ? 1.f : 0.f;
            tile[t][ty + 8 * i][tx] = sp;
            v = (v >= 1.f) ? 0.f : v;
        }
    }
    __syncthreads();
#pragma unroll
    for (int t = 0; t < TT; ++t)
#pragma unroll
        for (int i = 0; i < 4; ++i) {
            int l = t * NNv + n0 + ty + 8 * i;
            outT[((size_t)b * LLv + l) * Cdim + c0 + tx] =
                __float2half_rn(tile[t][tx][ty + 8 * i]);
        }
}

// -------------------- fused qkv GEMM + BN + LIF -----------------------------
__global__ void __launch_bounds__(256, 1) gemm_qkv_k(
    const __half* __restrict__ Wspl, const __half* __restrict__ BT,
    float* __restrict__ out, const float* __restrict__ scale,
    const float* __restrict__ shift) {

    extern __shared__ __align__(16) char smem[];
    uint32_t sb = smem_u32(smem);
    int tid = threadIdx.x;
    int lane = tid & 31, w = tid >> 5;
    int wm = w & 1, wn = w >> 1;

    int b = blockIdx.z;
    int tm = blockIdx.y * MT;
    int n0 = blockIdx.x * 64;
    const __half* Bt = BT + (size_t)b * LLv * CC;
    const size_t termstride = (size_t)CQKV * CC;
    const int KC = CC / KCH;   // 8

    float acc[4][8][4];
#pragma unroll
    for (int i = 0; i < 4; ++i)
#pragma unroll
        for (int j = 0; j < 8; ++j)
#pragma unroll
            for (int r = 0; r < 4; ++r) acc[i][j][r] = 0.f;

    auto issue_loads = [&](int c) {
        uint32_t base = sb + (uint32_t)(c % NSTAGE) * STAGE_BYTES;
        int k0 = c * KCH;
#pragma unroll
        for (int i = 0; i < 8; ++i) {
            int idx = i * 256 + tid;
            int term = idx >> 10;
            int within = idx & 1023;
            int row = within >> 3, c16 = within & 7;
            uint32_t o = (uint32_t)(row * 128 + c16 * 16);
            CP16(base + term * A_TERM_BYTES + SW(o),
                 Wspl + (size_t)term * termstride + (size_t)(tm + row) * CC + k0 + c16 * 8);
        }
#pragma unroll
        for (int i = 0; i < 8; ++i) {
            int idx = i * 256 + tid;
            int ridx = idx >> 3, c16 = idx & 7;
            int t = ridx >> 6, nloc = ridx & 63;
            int l = t * NNv + n0 + nloc;
            uint32_t o = (uint32_t)(ridx * 128 + c16 * 16);
            CP16(base + A_BYTES + SW(o),
                 Bt + (size_t)l * CC + k0 + c16 * 8);
        }
        CP_COMMIT();
    };

    issue_loads(0);
    issue_loads(1);

    int sub = lane >> 3;
    int lrow = lane & 7;

    for (int c = 0; c < KC; ++c) {
        uint32_t base = sb + (uint32_t)(c % NSTAGE) * STAGE_BYTES;
        if (c < KC - 1) CP_WAIT1(); else CP_WAIT0();
        __syncthreads();
        if (c + 2 < KC) issue_loads(c + 2);

        uint32_t abase = base;
        uint32_t bbase = base + A_BYTES;
#pragma unroll
        for (int ks = 0; ks < 4; ++ks) {
            uint32_t bfr[4][4];
#pragma unroll
            for (int t = 0; t < 4; ++t) {
                int rbase = t * 64 + wn * 16 + (sub >> 1) * 8 + lrow;
                uint32_t o = (uint32_t)(rbase * 128 + ks * 32 + (sub & 1) * 16);
                ldm_x4(bfr[t][0], bfr[t][1], bfr[t][2], bfr[t][3], bbase + SW(o));
            }
#pragma unroll
            for (int term = 0; term < TERMS; ++term) {
                uint32_t tb = abase + term * A_TERM_BYTES;
                uint32_t af[4][4];
#pragma unroll
                for (int mi = 0; mi < 4; ++mi) {
                    int m = wm * 64 + mi * 16 + (sub & 1) * 8 + lrow;
                    uint32_t o = (uint32_t)(m * 128 + ks * 32 + (sub >> 1) * 16);
                    ldm_x4(af[mi][0], af[mi][1], af[mi][2], af[mi][3], tb + SW(o));
                }
#pragma unroll
                for (int mi = 0; mi < 4; ++mi)
#pragma unroll
                    for (int nj = 0; nj < 8; ++nj)
                        mma16816(acc[mi][nj], af[mi][0], af[mi][1], af[mi][2], af[mi][3],
                                 bfr[nj >> 1][(nj & 1) * 2],
                                 bfr[nj >> 1][(nj & 1) * 2 + 1]);
            }
        }
    }

    // epilogue: BN + LIF over t, write spikes fp32
#pragma unroll
    for (int mi = 0; mi < 4; ++mi) {
#pragma unroll
        for (int h = 0; h < 2; ++h) {
            int co = tm + wm * 64 + mi * 16 + h * 8 + (lane >> 2);
            int sidx = ((co >> 9) << 11) | (co & 511);
            float scv = scale[sidx], shv = shift[sidx];
            float* op = out + ((size_t)b * CQKV + co) * LLv;
#pragma unroll
            for (int uh = 0; uh < 2; ++uh) {
                float v0 = 0.f, v1 = 0.f;
#pragma unroll
                for (int t = 0; t < 4; ++t) {
                    int nj = t * 2 + uh;
                    float x0 = acc[mi][nj][h * 2 + 0] * scv + shv;
                    float x1 = acc[mi][nj][h * 2 + 1] * scv + shv;
                    v0 += (x0 - v0) / 1.5f;
                    float s0 = (v0 >= 1.f) ? 1.f : 0.f; v0 = (v0 >= 1.f) ? 0.f : v0;
                    v1 += (x1 - v1) / 1.5f;
                    float s1 = (v1 >= 1.f) ? 1.f : 0.f; v1 = (v1 >= 1.f) ? 0.f : v1;
                    int l = t * NNv + n0 + wn * 16 + uh * 8 + (lane & 3) * 2;
                    float2 o2; o2.x = s0; o2.y = s1;
                    *(float2*)(op + l) = o2;
                }
            }
        }
    }
}

// -------------------- fused fc1 GEMM + BN + LIF -> s2T fp16 [B,L,HID] -------
// Same mainloop as qkv (Ci=512, t-major B columns); epilogue does LIF in regs,
// stages spikes in smem [256 l][128 co] fp16, then coalesced store to s2T.
__global__ void __launch_bounds__(256, 1) gemm_fc1_k(
    const __half* __restrict__ Wspl, const __half* __restrict__ BT,
    __half* __restrict__ s2T, const float* __restrict__ scale,
    const float* __restrict__ shift) {

    extern __shared__ __align__(16) char smem[];
    uint32_t sb = smem_u32(smem);
    int tid = threadIdx.x;
    int lane = tid & 31, w = tid >> 5;
    int wm = w & 1, wn = w >> 1;

    int b = blockIdx.z;
    int tm = blockIdx.y * MT;
    int n0 = blockIdx.x * 64;
    const __half* Bt = BT + (size_t)b * LLv * CC;
    const size_t termstride = (size_t)HIDN * CC;
    const int KC = CC / KCH;   // 8

    float acc[4][8][4];
#pragma unroll
    for (int i = 0; i < 4; ++i)
#pragma unroll
        for (int j = 0; j < 8; ++j)
#pragma unroll
            for (int r = 0; r < 4; ++r) acc[i][j][r] = 0.f;

    auto issue_loads = [&](int c) {
        uint32_t base = sb + (uint32_t)(c % NSTAGE) * STAGE_BYTES;
        int k0 = c * KCH;
#pragma unroll
        for (int i = 0; i < 8; ++i) {
            int idx = i * 256 + tid;
            int term = idx >> 10;
            int within = idx & 1023;
            int row = within >> 3, c16 = within & 7;
            uint32_t o = (uint32_t)(row * 128 + c16 * 16);
            CP16(base + term * A_TERM_BYTES + SW(o),
                 Wspl + (size_t)term * termstride + (size_t)(tm + row) * CC + k0 + c16 * 8);
        }
#pragma unroll
        for (int i = 0; i < 8; ++i) {
            int idx = i * 256 + tid;
            int ridx = idx >> 3, c16 = idx & 7;
            int t = ridx >> 6, nloc = ridx & 63;
            int l = t * NNv + n0 + nloc;
            uint32_t o = (uint32_t)(ridx * 128 + c16 * 16);
            CP16(base + A_BYTES + SW(o),
                 Bt + (size_t)l * CC + k0 + c16 * 8);
        }
        CP_COMMIT();
    };

    issue_loads(0);
    issue_loads(1);

    int sub = lane >> 3;
    int lrow = lane & 7;

    for (int c = 0; c < KC; ++c) {
        uint32_t base = sb + (uint32_t)(c % NSTAGE) * STAGE_BYTES;
        if (c < KC - 1) CP_WAIT1(); else CP_WAIT0();
        __syncthreads();
        if (c + 2 < KC) issue_loads(c + 2);

        uint32_t abase = base;
        uint32_t bbase = base + A_BYTES;
#pragma unroll
        for (int ks = 0; ks < 4; ++ks) {
            uint32_t bfr[4][4];
#pragma unroll
            for (int t = 0; t < 4; ++t) {
                int rbase = t * 64 + wn * 16 + (sub >> 1) * 8 + lrow;
                uint32_t o = (uint32_t)(rbase * 128 + ks * 32 + (sub & 1) * 16);
                ldm_x4(bfr[t][0], bfr[t][1], bfr[t][2], bfr[t][3], bbase + SW(o));
            }
#pragma unroll
            for (int term = 0; term < TERMS; ++term) {
                uint32_t tb = abase + term * A_TERM_BYTES;
                uint32_t af[4][4];
#pragma unroll
                for (int mi = 0; mi < 4; ++mi) {
                    int m = wm * 64 + mi * 16 + (sub & 1) * 8 + lrow;
                    uint32_t o = (uint32_t)(m * 128 + ks * 32 + (sub >> 1) * 16);
                    ldm_x4(af[mi][0], af[mi][1], af[mi][2], af[mi][3], tb + SW(o));
                }
#pragma unroll
                for (int mi = 0; mi < 4; ++mi)
#pragma unroll
                    for (int nj = 0; nj < 8; ++nj)
                        mma16816(acc[mi][nj], af[mi][0], af[mi][1], af[mi][2], af[mi][3],
                                 bfr[nj >> 1][(nj & 1) * 2],
                                 bfr[nj >> 1][(nj & 1) * 2 + 1]);
            }
        }
    }

    // epilogue: BN + LIF over t in regs, stage spikes in smem [ridx 256][co 128]
    __syncthreads();   // all warps done reading B smem
    __half* st = (__half*)smem;
#pragma unroll
    for (int mi = 0; mi < 4; ++mi) {
#pragma unroll
        for (int h = 0; h < 2; ++h) {
            int col = wm * 64 + mi * 16 + h * 8 + (lane >> 2);   // co - tm
            int co = tm + col;
            float scv = scale[co], shv = shift[co];
#pragma unroll
            for (int uh = 0; uh < 2; ++uh) {
                float v0 = 0.f, v1 = 0.f;
#pragma unroll
                for (int t = 0; t < 4; ++t) {
                    int nj = t * 2 + uh;
                    float x0 = acc[mi][nj][h * 2 + 0] * scv + shv;
                    float x1 = acc[mi][nj][h * 2 + 1] * scv + shv;
                    v0 += (x0 - v0) / 1.5f;
                    float s0 = (v0 >= 1.f) ? 1.f : 0.f; v0 = (v0 >= 1.f) ? 0.f : v0;
                    v1 += (x1 - v1) / 1.5f;
                    float s1 = (v1 >= 1.f) ? 1.f : 0.f; v1 = (v1 >= 1.f) ? 0.f : v1;
                    int ridx = t * 64 + wn * 16 + uh * 8 + (lane & 3) * 2;
                    st[ridx * 128 + col] = __float2half_rn(s0);
                    st[(ridx + 1) * 128 + col] = __float2half_rn(s1);
                }
            }
        }
    }
    __syncthreads();
    // coalesced store: row ridx -> l = t*512 + n0 + nloc
    for (int i = tid; i < 256 * 16; i += 256) {
        int row = i >> 4, ch = i & 15;
        int t = row >> 6, nloc = row & 63;
        int l = t * NNv + n0 + nloc;
        uint4 v = *(uint4*)&st[row * 128 + ch * 8];
        *(uint4*)(s2T + ((size_t)b * LLv + l) * HIDN + tm + ch * 8) = v;
    }
}

// -------------------- plain mma GEMM (proj/fc2) -----------------------------
__global__ void __launch_bounds__(256, 1) gemm_mma_k(
    const __half* __restrict__ Wspl, const __half* __restrict__ BT,
    float* __restrict__ out, const float* __restrict__ scale, const float* __restrict__ shift,
    const float* __restrict__ resid, int Co, int Ci) {

    extern __shared__ __align__(16) char smem[];
    uint32_t sb = smem_u32(smem);
    int tid = threadIdx.x;
    int lane = tid & 31, w = tid >> 5;
    int wm = w & 1, wn = w >> 1;

    int b = blockIdx.z;
    int tm = blockIdx.y * MT;
    int tn = blockIdx.x * NT;
    const __half* Bt = BT + (size_t)b * LLv * Ci;
    const size_t termstride = (size_t)Co * Ci;
    const int KC = Ci / KCH;

    float acc[4][8][4];
#pragma unroll
    for (int i = 0; i < 4; ++i)
#pragma unroll
        for (int j = 0; j < 8; ++j)
#pragma unroll
            for (int r = 0; r < 4; ++r) acc[i][j][r] = 0.f;

    auto issue_loads = [&](int c) {
        uint32_t base = sb + (uint32_t)(c % NSTAGE) * STAGE_BYTES;
        int k0 = c * KCH;
#pragma unroll
        for (int i = 0; i < 8; ++i) {
            int idx = i * 256 + tid;
            int term = idx >> 10;
            int within = idx & 1023;
            int row = within >> 3, c16 = within & 7;
            uint32_t o = (uint32_t)(row * 128 + c16 * 16);
            CP16(base + term * A_TERM_BYTES + SW(o),
                 Wspl + (size_t)term * termstride + (size_t)(tm + row) * Ci + k0 + c16 * 8);
        }
#pragma unroll
        for (int i = 0; i < 8; ++i) {
            int idx = i * 256 + tid;
            int row = idx >> 3, c16 = idx & 7;
            uint32_t o = (uint32_t)(row * 128 + c16 * 16);
            CP16(base + A_BYTES + SW(o),
                 Bt + (size_t)(tn + row) * Ci + k0 + c16 * 8);
        }
        CP_COMMIT();
    };

    issue_loads(0);
    issue_loads(1);

    int sub = lane >> 3;
    int lrow = lane & 7;

    for (int c = 0; c < KC; ++c) {
        uint32_t base = sb + (uint32_t)(c % NSTAGE) * STAGE_BYTES;
        if (c < KC - 1) CP_WAIT1(); else CP_WAIT0();
        __syncthreads();
        if (c + 2 < KC) issue_loads(c + 2);

        uint32_t abase = base;
        uint32_t bbase = base + A_BYTES;
#pragma unroll
        for (int ks = 0; ks < 4; ++ks) {
            uint32_t bfr[4][4];
#pragma unroll
            for (int ni = 0; ni < 4; ++ni) {
                int n = wn * 64 + ni * 16 + (sub >> 1) * 8 + lrow;
                uint32_t o = (uint32_t)(n * 128 + ks * 32 + (sub & 1) * 16);
                ldm_x4(bfr[ni][0], bfr[ni][1], bfr[ni][2], bfr[ni][3], bbase + SW(o));
            }
#pragma unroll
            for (int term = 0; term < TERMS; ++term) {
                uint32_t tb = abase + term * A_TERM_BYTES;
                uint32_t af[4][4];
#pragma unroll
                for (int mi = 0; mi < 4; ++mi) {
                    int m = wm * 64 + mi * 16 + (sub & 1) * 8 + lrow;
                    uint32_t o = (uint32_t)(m * 128 + ks * 32 + (sub >> 1) * 16);
                    ldm_x4(af[mi][0], af[mi][1], af[mi][2], af[mi][3], tb + SW(o));
                }
#pragma unroll
                for (int mi = 0; mi < 4; ++mi)
#pragma unroll
                    for (int nj = 0; nj < 8; ++nj)
                        mma16816(acc[mi][nj], af[mi][0], af[mi][1], af[mi][2], af[mi][3],
                                 bfr[nj >> 1][(nj & 1) * 2],
                                 bfr[nj >> 1][(nj & 1) * 2 + 1]);
            }
        }
    }

#pragma unroll
    for (int mi = 0; mi < 4; ++mi) {
#pragma unroll
        for (int h = 0; h < 2; ++h) {
            int co = tm + wm * 64 + mi * 16 + h * 8 + (lane >> 2);
            float scv = scale ? scale[co] : 1.f;
            float shv = shift ? shift[co] : 0.f;
            float* op = out + ((size_t)b * Co + co) * LLv + tn;
            const float* rp = resid ? resid + ((size_t)b * Co + co) * LLv + tn : nullptr;
#pragma unroll
            for (int nj = 0; nj < 8; ++nj) {
                int col = wn * 64 + nj * 8 + (lane & 3) * 2;
                float2 o;
                o.x = acc[mi][nj][h * 2 + 0] * scv + shv;
                o.y = acc[mi][nj][h * 2 + 1] * scv + shv;
                if (rp) {
                    float2 rv = *(const float2*)(rp + col);
                    o.x += rv.x; o.y += rv.y;
                }
                *(float2*)(op + col) = o;
            }
        }
    }
}

// -------------------- M partials = k^T v over L-slices ----------------------
__global__ void __launch_bounds__(256) kv_outer_k(
    const float* __restrict__ skv, float* __restrict__ Mp) {
    int bh = blockIdx.x;                  // 0..31
    int spl = blockIdx.y;                 // 0..15
    int b = bh >> 3, h = bh & 7;
    const float* K = skv + ((size_t)b * CQKV + 512 + h * HD) * LLv;
    const float* V = skv + ((size_t)b * CQKV + 1024 + h * HD) * LLv;
    __shared__ float Ks[64][65];
    __shared__ float Vs[64][65];
    float acc[4][4];
#pragma unroll
    for (int i = 0; i < 4; ++i)
#pragma unroll
        for (int j = 0; j < 4; ++j) acc[i][j] = 0.f;
    int tr = threadIdx.x >> 4, tc = threadIdx.x & 15;
    int row = threadIdx.x >> 2, cb = (threadIdx.x & 3) * 16;
    int lbeg = spl * (LLv / KVSPL);
    for (int l0 = lbeg; l0 < lbeg + LLv / KVSPL; l0 += 64) {
        __syncthreads();
#pragma unroll
        for (int u = 0; u < 16; u += 4) {
            float4 kv = *(const float4*)&K[(size_t)row * LLv + l0 + cb + u];
            Ks[row][cb + u] = kv.x; Ks[row][cb + u + 1] = kv.y;
            Ks[row][cb + u + 2] = kv.z; Ks[row][cb + u + 3] = kv.w;
            float4 vv = *(const float4*)&V[(size_t)row * LLv + l0 + cb + u];
            Vs[row][cb + u] = vv.x; Vs[row][cb + u + 1] = vv.y;
            Vs[row][cb + u + 2] = vv.z; Vs[row][cb + u + 3] = vv.w;
        }
        __syncthreads();
#pragma unroll
        for (int ll = 0; ll < 64; ++ll) {
            float a[4], c[4];
#pragma unroll
            for (int i = 0; i < 4; ++i) a[i] = Ks[tr * 4 + i][ll];
#pragma unroll
            for (int i = 0; i < 4; ++i) c[i] = Vs[tc * 4 + i][ll];
#pragma unroll
            for (int i = 0; i < 4; ++i)
#pragma unroll
                for (int j = 0; j < 4; ++j) acc[i][j] += a[i] * c[j];
        }
    }
    float* Mo = Mp + ((size_t)spl * 32 + bh) * (HD * HD);
#pragma unroll
    for (int i = 0; i < 4; ++i)
#pragma unroll
        for (int j = 0; j < 4; ++j)
            Mo[(tr * 4 + i) * HD + tc * 4 + j] = acc[i][j];
}

// -------------------- o = q @ (sum Mp) -> spike -> soT fp16 -----------------
__global__ void __launch_bounds__(256) qm_spike_k(
    const float* __restrict__ skv, const float* __restrict__ Mp, __half* __restrict__ soT) {
    int bh = blockIdx.y;
    int b = bh >> 3, h = bh & 7;
    int l = blockIdx.x * 256 + threadIdx.x;
    __shared__ float Ms[HD * HD];
#pragma unroll
    for (int u = 0; u < 16; ++u) {
        int idx = u * 256 + threadIdx.x;
        float s = 0.f;
#pragma unroll
        for (int sp = 0; sp < KVSPL; ++sp)
            s += Mp[((size_t)sp * 32 + bh) * (HD * HD) + idx];
        Ms[idx] = s;
    }
    __syncthreads();
    const float* Q = skv + ((size_t)b * CQKV + h * HD) * LLv + l;
    float acc[HD];
#pragma unroll
    for (int jp = 0; jp < HD; ++jp) acc[jp] = 0.f;
    for (int j = 0; j < HD; ++j) {
        float qv = Q[(size_t)j * LLv];
#pragma unroll
        for (int jp = 0; jp < HD; ++jp) acc[jp] += qv * Ms[j * HD + jp];
    }
    __half* O = soT + ((size_t)b * LLv + l) * CC + h * HD;
#pragma unroll
    for (int jp = 0; jp < HD; ++jp) {
        float o = acc[jp] * 0.125f;
        O[jp] = __float2half_rn(((o / 1.5f - 1.f) >= 0.f) ? 1.f : 0.f);
    }
}

// ---------------------------------------------------------------------------
extern "C" void kernel_launch(void* const* d_in, const int* in_sizes, int n_in,
                              void* d_out, int out_size) {
    const float* x       = (const float*)d_in[0];
    const float* attn_bn = (const float*)d_in[1];
    const float* q_w     = (const float*)d_in[2];
    const float* q_bn    = (const float*)d_in[3];
    const float* k_w     = (const float*)d_in[4];
    const float* k_bn    = (const float*)d_in[5];
    const float* v_w     = (const float*)d_in[6];
    const float* v_bn    = (const float*)d_in[7];
    const float* proj_w  = (const float*)d_in[8];
    const float* proj_b  = (const float*)d_in[9];
    const float* mlp_bn  = (const float*)d_in[10];
    const float* fc1_w   = (const float*)d_in[11];
    const float* fc1_b   = (const float*)d_in[12];
    const float* fc1_bn  = (const float*)d_in[13];
    const float* fc2_w   = (const float*)d_in[14];
    const float* fc2_b   = (const float*)d_in[15];
    float* out = (float*)d_out;

    float *skv, *x1, *Mp, *scale, *shift;
    __half *xqT, *soT, *s2T, *w;
    cudaGetSymbolAddress((void**)&skv, g_skv);
    cudaGetSymbolAddress((void**)&x1,  g_x1);
    cudaGetSymbolAddress((void**)&Mp,  g_Mp);
    cudaGetSymbolAddress((void**)&scale, g_scale);
    cudaGetSymbolAddress((void**)&shift, g_shift);
    cudaGetSymbolAddress((void**)&xqT, g_xqT);
    cudaGetSymbolAddress((void**)&soT, g_soT);
    cudaGetSymbolAddress((void**)&s2T, g_s2T);
    cudaGetSymbolAddress((void**)&w,   g_w);

    cudaFuncSetAttribute(gemm_mma_k, cudaFuncAttributeMaxDynamicSharedMemorySize, DYN_SMEM);
    cudaFuncSetAttribute(gemm_qkv_k, cudaFuncAttributeMaxDynamicSharedMemorySize, DYN_SMEM);
    cudaFuncSetAttribute(gemm_fc1_k, cudaFuncAttributeMaxDynamicSharedMemorySize, DYN_SMEM);

    __half* wqkv = w;                       // [2][1536][512]
    __half* wp   = w + 6 * (size_t)SZ;      // [2][512][512]
    __half* wf1  = w + 8 * (size_t)SZ;      // [2][2048][512]
    __half* wf2  = wf1 + 2 * (size_t)SZH;   // [2][512][2048]

    bnprep_all<<<dim3(8, 6), 256>>>(attn_bn, q_bn, k_bn, v_bn, mlp_bn, fc1_bn, fc1_b,
                                    scale, shift);
    wsplit_all<<<(4 * SZ + 2 * SZH) / 256, 256>>>(q_w, k_w, v_w, proj_w, fc1_w, fc2_w,
                                                  wqkv, wp, wf1, wf2);

    dim3 ltr(32, 8);
    dim3 gtr512(16, 16, BB);
    dim3 gg512(LLv / NT, CC / MT, BB);      // (8,4,4)

    // attn input spikes (BN_attn + LIF) -> xqT fp16 [B,L,C]
    lif_tr_k<<<gtr512, ltr>>>(x, xqT, scale, shift, CC);

    // fused q/k/v GEMM + BN + LIF -> skv spikes fp32 [B,1536,L]
    gemm_qkv_k<<<dim3(8, 12, 4), 256, DYN_SMEM>>>(wqkv, xqT, skv,
                                                  scale + 2048, shift + 2048);

    // attention: exact q (k^T v) with split-L partials
    kv_outer_k<<<dim3(32, KVSPL), 256>>>(skv, Mp);
    qm_spike_k<<<dim3(8, 32), 256>>>(skv, Mp, soT);

    // proj + residual -> x1
    gemm_mma_k<<<gg512, 256, DYN_SMEM>>>(wp, soT, x1, nullptr, proj_b, x, CC, CC);

    // MLP: BN+LIF -> xqT, fc1 fused (GEMM+BN+LIF -> s2T fp16), fc2 + residual
    lif_tr_k<<<gtr512, ltr>>>(x1, xqT, scale + 4 * 2048, shift + 4 * 2048, CC);
    gemm_fc1_k<<<dim3(8, 16, 4), 256, DYN_SMEM>>>(wf1, xqT, s2T,
                                                  scale + 5 * 2048, shift + 5 * 2048);
    gemm_mma_k<<<gg512, 256, DYN_SMEM>>>(wf2, s2T, out, nullptr, fc2_b, x1, CC, HIDN);
}

// round 10
// speedup vs baseline: 4.5874x; 1.0229x over previous
#include <cuda_runtime.h>
#include <cuda_fp16.h>
#include <cstdint>
#include <cstddef>

// ---------------------------------------------------------------------------
// SpikingTransformerBlock, mma.sync fp16 2-term path (base sm_100 compatible)
// R10: GEMMs at 2 CTAs/SM (128 thr, 128x128 tile, KCH=32, 3-stage pipeline)
// for cross-CTA latency hiding. qkv/fc1 keep fused BN+LIF epilogues.
// ---------------------------------------------------------------------------

#define BB 4
#define CC 512
#define TT 4
#define NNv 512
#define LLv 2048
#define HIDN 2048
#define NH 8
#define HD 64
#define CQKV 1536
#define KVSPL 16

#define MT 128
#define NTP 128
#define KCH 32
#define TERMS 2
#define A_TERM_BYTES (MT * KCH * 2)           // 8192
#define A_BYTES (TERMS * A_TERM_BYTES)        // 16384
#define B_BYTES (NTP * KCH * 2)               // 8192
#define STAGE_BYTES (A_BYTES + B_BYTES)       // 24576
#define NSTAGE 3
#define DYN_SMEM (NSTAGE * STAGE_BYTES)       // 73728

#define SW(o) ((o) ^ (((o) >> 3) & 0x70))

#define SZ   (CC * CC)      // 262144
#define SZH  (HIDN * CC)    // 1048576

// -------------------- device scratch ---------------------------------------
__device__ float g_skv[(size_t)BB * CQKV * LLv];
__device__ float g_x1 [(size_t)BB * CC * LLv];
__device__ float g_Mp [(size_t)KVSPL * BB * NH * HD * HD];
__device__ __half g_xqT[(size_t)BB * LLv * CC];
__device__ __half g_soT[(size_t)BB * LLv * CC];
__device__ __half g_s2T[(size_t)BB * LLv * HIDN];
__device__ __half g_w[8 * SZ + 4 * SZH];
__device__ float g_scale[6 * 2048];
__device__ float g_shift[6 * 2048];

// -------------------- helpers ----------------------------------------------
__device__ __forceinline__ uint32_t smem_u32(const void* p) {
    uint32_t a;
    asm("{ .reg .u64 t; cvta.to.shared.u64 t, %1; cvt.u32.u64 %0, t; }" : "=r"(a) : "l"(p));
    return a;
}
#define CP16(sa, gp) \
    asm volatile("cp.async.cg.shared.global [%0], [%1], 16;" :: "r"(sa), "l"(gp) : "memory")
#define CP_COMMIT() asm volatile("cp.async.commit_group;" ::: "memory")
#define CP_WAIT1() asm volatile("cp.async.wait_group 1;" ::: "memory")
#define CP_WAIT0() asm volatile("cp.async.wait_group 0;" ::: "memory")

__device__ __forceinline__ void ldm_x4(uint32_t& r0, uint32_t& r1, uint32_t& r2, uint32_t& r3,
                                       uint32_t addr) {
    asm volatile("ldmatrix.sync.aligned.m8n8.x4.shared.b16 {%0,%1,%2,%3}, [%4];"
                 : "=r"(r0), "=r"(r1), "=r"(r2), "=r"(r3) : "r"(addr));
}
__device__ __forceinline__ void mma16816(float* c, uint32_t a0, uint32_t a1, uint32_t a2,
                                         uint32_t a3, uint32_t b0, uint32_t b1) {
    asm volatile("mma.sync.aligned.m16n8k16.row.col.f32.f16.f16.f32 "
                 "{%0,%1,%2,%3},{%4,%5,%6,%7},{%8,%9},{%0,%1,%2,%3};"
                 : "+f"(c[0]), "+f"(c[1]), "+f"(c[2]), "+f"(c[3])
                 : "r"(a0), "r"(a1), "r"(a2), "r"(a3), "r"(b0), "r"(b1));
}

// t-major row<->l map for NTP=128 tiles: r in [0,128)
// l = ((r>>4)&3)*512 + n0 + (r>>6)*16 + (r&15)
__device__ __forceinline__ int tmaj_l(int r, int n0) {
    return ((r >> 4) & 3) * NNv + n0 + ((r >> 6) << 4) + (r & 15);
}

// -------------------- merged BN fold ----------------------------------------
__global__ void bnprep_all(const float* __restrict__ p0, const float* __restrict__ p1,
                           const float* __restrict__ p2, const float* __restrict__ p3,
                           const float* __restrict__ p4, const float* __restrict__ p5,
                           const float* __restrict__ fc1b,
                           float* __restrict__ scale, float* __restrict__ shift) {
    int slot = blockIdx.y;
    int Cdim = (slot == 5) ? 2048 : 512;
    int c = blockIdx.x * 256 + threadIdx.x;
    if (c >= Cdim) return;
    const float* p = (slot == 0) ? p0 : (slot == 1) ? p1 : (slot == 2) ? p2 :
                     (slot == 3) ? p3 : (slot == 4) ? p4 : p5;
    float g = p[c], be = p[Cdim + c], m = p[2 * Cdim + c], va = p[3 * Cdim + c];
    float inv = g / sqrtf(va + 1e-5f);
    float sh = be - m * inv;
    if (slot == 5) sh += fc1b[c] * inv;
    scale[slot * 2048 + c] = inv;
    shift[slot * 2048 + c] = sh;
}

// -------------------- merged weight split -----------------------------------
__global__ void wsplit_all(const float* __restrict__ qw, const float* __restrict__ kw,
                           const float* __restrict__ vw, const float* __restrict__ pw,
                           const float* __restrict__ f1, const float* __restrict__ f2,
                           __half* __restrict__ wqkv, __half* __restrict__ wp,
                           __half* __restrict__ wf1, __half* __restrict__ wf2) {
    int i = blockIdx.x * 256 + threadIdx.x;
    const float* src; __half *dhi, *dlo;
    if (i < 3 * SZ) {
        int seg = i / SZ, j = i - seg * SZ;
        src = (seg == 0) ? qw + j : (seg == 1) ? kw + j : vw + j;
        dhi = wqkv + seg * SZ + j; dlo = wqkv + 3 * SZ + seg * SZ + j;
    } else if (i < 4 * SZ) {
        int j = i - 3 * SZ;
        src = pw + j; dhi = wp + j; dlo = wp + SZ + j;
    } else if (i < 4 * SZ + SZH) {
        int j = i - 4 * SZ;
        src = f1 + j; dhi = wf1 + j; dlo = wf1 + SZH + j;
    } else {
        int j = i - 4 * SZ - SZH;
        if (j >= SZH) return;
        src = f2 + j; dhi = wf2 + j; dlo = wf2 + SZH + j;
    }
    float x = *src;
    __half h = __float2half_rn(x);
    *dhi = h;
    *dlo = __float2half_rn(x - __half2float(h));
}

// -------------------- LIF (+opt BN) -> transposed fp16 spikes ---------------
__global__ void lif_tr_k(const float* __restrict__ in, __half* __restrict__ outT,
                         const float* __restrict__ scale, const float* __restrict__ shift,
                         int Cdim) {
    __shared__ float tile[TT][32][33];
    int b = blockIdx.z, c0 = blockIdx.y * 32, n0 = blockIdx.x * 32;
    int tx = threadIdx.x, ty = threadIdx.y;
#pragma unroll
    for (int i = 0; i < 4; ++i) {
        int c = c0 + ty + 8 * i;
        float sc = scale ? scale[c] : 1.f;
        float sh = shift ? shift[c] : 0.f;
        size_t base = ((size_t)b * Cdim + c) * LLv + n0 + tx;
        float v = 0.f;
#pragma unroll
        for (int t = 0; t < TT; ++t) {
            float xv = in[base + (size_t)t * NNv] * sc + sh;
            v += (xv - v) / 1.5f;
            float sp = (v >= 1.f) ? 1.f : 0.f;
            tile[t][ty + 8 * i][tx] = sp;
            v = (v >= 1.f) ? 0.f : v;
        }
    }
    __syncthreads();
#pragma unroll
    for (int t = 0; t < TT; ++t)
#pragma unroll
        for (int i = 0; i < 4; ++i) {
            int l = t * NNv + n0 + ty + 8 * i;
            outT[((size_t)b * LLv + l) * Cdim + c0 + tx] =
                __float2half_rn(tile[t][tx][ty + 8 * i]);
        }
}

// ============= GEMM mainloop macro (128 thr, 128x128 tile, KCH=32) ==========
// Requires: sb, tid, lane, wm, wn, sub, lrow, acc, issue_loads, KC.
#define GEMM_MAINLOOP()                                                         \
    issue_loads(0);                                                             \
    issue_loads(1);                                                             \
    for (int c = 0; c < KC; ++c) {                                              \
        uint32_t base = sb + (uint32_t)(c % NSTAGE) * STAGE_BYTES;              \
        if (c < KC - 1) CP_WAIT1(); else CP_WAIT0();                            \
        __syncthreads();                                                        \
        if (c + 2 < KC) issue_loads(c + 2);                                     \
        uint32_t abase = base;                                                  \
        uint32_t bbase = base + A_BYTES;                                        \
        _Pragma("unroll")                                                       \
        for (int ks = 0; ks < 2; ++ks) {                                        \
            uint32_t bfr[4][4];                                                 \
            _Pragma("unroll")                                                   \
            for (int ni = 0; ni < 4; ++ni) {                                    \
                int n = wn * 64 + ni * 16 + (sub >> 1) * 8 + lrow;              \
                uint32_t o = (uint32_t)(n * 64 + ks * 32 + (sub & 1) * 16);     \
                ldm_x4(bfr[ni][0], bfr[ni][1], bfr[ni][2], bfr[ni][3],          \
                       bbase + SW(o));                                          \
            }                                                                   \
            _Pragma("unroll")                                                   \
            for (int term = 0; term < TERMS; ++term) {                          \
                uint32_t tb = abase + term * A_TERM_BYTES;                      \
                uint32_t af[4][4];                                              \
                _Pragma("unroll")                                               \
                for (int mi = 0; mi < 4; ++mi) {                                \
                    int m = wm * 64 + mi * 16 + (sub & 1) * 8 + lrow;           \
                    uint32_t o = (uint32_t)(m * 64 + ks * 32 + (sub >> 1) * 16);\
                    ldm_x4(af[mi][0], af[mi][1], af[mi][2], af[mi][3],          \
                           tb + SW(o));                                         \
                }                                                               \
                _Pragma("unroll")                                               \
                for (int mi = 0; mi < 4; ++mi)                                  \
                    _Pragma("unroll")                                           \
                    for (int nj = 0; nj < 8; ++nj)                              \
                        mma16816(acc[mi][nj], af[mi][0], af[mi][1], af[mi][2],  \
                                 af[mi][3], bfr[nj >> 1][(nj & 1) * 2],         \
                                 bfr[nj >> 1][(nj & 1) * 2 + 1]);               \
            }                                                                   \
        }                                                                       \
    }

#define GEMM_PREAMBLE()                                                         \
    extern __shared__ __align__(16) char smem[];                                \
    uint32_t sb = smem_u32(smem);                                               \
    int tid = threadIdx.x;                                                      \
    int lane = tid & 31, w = tid >> 5;                                          \
    int wm = w & 1, wn = w >> 1;                                                \
    int sub = lane >> 3, lrow = lane & 7;                                       \
    float acc[4][8][4];                                                         \
    _Pragma("unroll")                                                           \
    for (int i = 0; i < 4; ++i)                                                 \
        _Pragma("unroll")                                                       \
        for (int j = 0; j < 8; ++j)                                             \
            _Pragma("unroll")                                                   \
            for (int r = 0; r < 4; ++r) acc[i][j][r] = 0.f;

// -------------------- fused qkv GEMM + BN + LIF (t-major cols) --------------
__global__ void __launch_bounds__(128, 2) gemm_qkv_k(
    const __half* __restrict__ Wspl, const __half* __restrict__ BT,
    float* __restrict__ out, const float* __restrict__ scale,
    const float* __restrict__ shift) {

    GEMM_PREAMBLE();
    int b = blockIdx.z;
    int tm = blockIdx.y * MT;
    int n0 = blockIdx.x * 32;
    const __half* Bt = BT + (size_t)b * LLv * CC;
    const size_t termstride = (size_t)CQKV * CC;
    const int KC = CC / KCH;   // 16

    auto issue_loads = [&](int c) {
        uint32_t base = sb + (uint32_t)(c % NSTAGE) * STAGE_BYTES;
        int k0 = c * KCH;
#pragma unroll
        for (int i = 0; i < 8; ++i) {          // A: 2 x 128 x 4 = 1024 chunks
            int idx = i * 128 + tid;
            int term = idx >> 9;
            int within = idx & 511;
            int row = within >> 2, c16 = within & 3;
            uint32_t o = (uint32_t)(row * 64 + c16 * 16);
            CP16(base + term * A_TERM_BYTES + SW(o),
                 Wspl + (size_t)term * termstride + (size_t)(tm + row) * CC + k0 + c16 * 8);
        }
#pragma unroll
        for (int i = 0; i < 4; ++i) {          // B: 128 x 4 = 512 chunks, t-major
            int idx = i * 128 + tid;
            int ridx = idx >> 2, c16 = idx & 3;
            int l = tmaj_l(ridx, n0);
            uint32_t o = (uint32_t)(ridx * 64 + c16 * 16);
            CP16(base + A_BYTES + SW(o),
                 Bt + (size_t)l * CC + k0 + c16 * 8);
        }
        CP_COMMIT();
    };

    GEMM_MAINLOOP();

    // epilogue: BN + LIF over t (nj = t*2 + uh), write spikes fp32
#pragma unroll
    for (int mi = 0; mi < 4; ++mi) {
#pragma unroll
        for (int h = 0; h < 2; ++h) {
            int co = tm + wm * 64 + mi * 16 + h * 8 + (lane >> 2);
            int sidx = ((co >> 9) << 11) | (co & 511);
            float scv = scale[sidx], shv = shift[sidx];
            float* op = out + ((size_t)b * CQKV + co) * LLv;
#pragma unroll
            for (int uh = 0; uh < 2; ++uh) {
                float v0 = 0.f, v1 = 0.f;
#pragma unroll
                for (int t = 0; t < 4; ++t) {
                    int nj = t * 2 + uh;
                    float x0 = acc[mi][nj][h * 2 + 0] * scv + shv;
                    float x1 = acc[mi][nj][h * 2 + 1] * scv + shv;
                    v0 += (x0 - v0) / 1.5f;
                    float s0 = (v0 >= 1.f) ? 1.f : 0.f; v0 = (v0 >= 1.f) ? 0.f : v0;
                    v1 += (x1 - v1) / 1.5f;
                    float s1 = (v1 >= 1.f) ? 1.f : 0.f; v1 = (v1 >= 1.f) ? 0.f : v1;
                    int l = t * NNv + n0 + wn * 16 + uh * 8 + (lane & 3) * 2;
                    float2 o2; o2.x = s0; o2.y = s1;
                    *(float2*)(op + l) = o2;
                }
            }
        }
    }
}

// -------------------- fused fc1 GEMM + BN + LIF -> s2T fp16 -----------------
__global__ void __launch_bounds__(128, 2) gemm_fc1_k(
    const __half* __restrict__ Wspl, const __half* __restrict__ BT,
    __half* __restrict__ s2T, const float* __restrict__ scale,
    const float* __restrict__ shift) {

    GEMM_PREAMBLE();
    int b = blockIdx.z;
    int tm = blockIdx.y * MT;
    int n0 = blockIdx.x * 32;
    const __half* Bt = BT + (size_t)b * LLv * CC;
    const size_t termstride = (size_t)HIDN * CC;
    const int KC = CC / KCH;   // 16

    auto issue_loads = [&](int c) {
        uint32_t base = sb + (uint32_t)(c % NSTAGE) * STAGE_BYTES;
        int k0 = c * KCH;
#pragma unroll
        for (int i = 0; i < 8; ++i) {
            int idx = i * 128 + tid;
            int term = idx >> 9;
            int within = idx & 511;
            int row = within >> 2, c16 = within & 3;
            uint32_t o = (uint32_t)(row * 64 + c16 * 16);
            CP16(base + term * A_TERM_BYTES + SW(o),
                 Wspl + (size_t)term * termstride + (size_t)(tm + row) * CC + k0 + c16 * 8);
        }
#pragma unroll
        for (int i = 0; i < 4; ++i) {
            int idx = i * 128 + tid;
            int ridx = idx >> 2, c16 = idx & 3;
            int l = tmaj_l(ridx, n0);
            uint32_t o = (uint32_t)(ridx * 64 + c16 * 16);
            CP16(base + A_BYTES + SW(o),
                 Bt + (size_t)l * CC + k0 + c16 * 8);
        }
        CP_COMMIT();
    };

    GEMM_MAINLOOP();

    // epilogue: BN + LIF in regs, stage spikes in smem [r 0..127][co 0..127]
    __syncthreads();
    __half* st = (__half*)smem;
#pragma unroll
    for (int mi = 0; mi < 4; ++mi) {
#pragma unroll
        for (int h = 0; h < 2; ++h) {
            int col = wm * 64 + mi * 16 + h * 8 + (lane >> 2);
            int co = tm + col;
            float scv = scale[co], shv = shift[co];
#pragma unroll
            for (int uh = 0; uh < 2; ++uh) {
                float v0 = 0.f, v1 = 0.f;
#pragma unroll
                for (int t = 0; t < 4; ++t) {
                    int nj = t * 2 + uh;
                    float x0 = acc[mi][nj][h * 2 + 0] * scv + shv;
                    float x1 = acc[mi][nj][h * 2 + 1] * scv + shv;
                    v0 += (x0 - v0) / 1.5f;
                    float s0 = (v0 >= 1.f) ? 1.f : 0.f; v0 = (v0 >= 1.f) ? 0.f : v0;
                    v1 += (x1 - v1) / 1.5f;
                    float s1 = (v1 >= 1.f) ? 1.f : 0.f; v1 = (v1 >= 1.f) ? 0.f : v1;
                    int r = wn * 64 + t * 16 + uh * 8 + (lane & 3) * 2;
                    st[r * 128 + col] = __float2half_rn(s0);
                    st[(r + 1) * 128 + col] = __float2half_rn(s1);
                }
            }
        }
    }
    __syncthreads();
    // coalesced store: row r -> l via t-major map
    for (int i = tid; i < 128 * 16; i += 128) {
        int row = i >> 4, ch = i & 15;
        int l = tmaj_l(row, n0);
        uint4 v = *(uint4*)&st[row * 128 + ch * 8];
        *(uint4*)(s2T + ((size_t)b * LLv + l) * HIDN + tm + ch * 8) = v;
    }
}

// -------------------- plain mma GEMM (proj/fc2) -----------------------------
__global__ void __launch_bounds__(128, 2) gemm_mma_k(
    const __half* __restrict__ Wspl, const __half* __restrict__ BT,
    float* __restrict__ out, const float* __restrict__ scale, const float* __restrict__ shift,
    const float* __restrict__ resid, int Co, int Ci) {

    GEMM_PREAMBLE();
    int b = blockIdx.z;
    int tm = blockIdx.y * MT;
    int tn = blockIdx.x * NTP;
    const __half* Bt = BT + (size_t)b * LLv * Ci;
    const size_t termstride = (size_t)Co * Ci;
    const int KC = Ci / KCH;

    auto issue_loads = [&](int c) {
        uint32_t base = sb + (uint32_t)(c % NSTAGE) * STAGE_BYTES;
        int k0 = c * KCH;
#pragma unroll
        for (int i = 0; i < 8; ++i) {
            int idx = i * 128 + tid;
            int term = idx >> 9;
            int within = idx & 511;
            int row = within >> 2, c16 = within & 3;
            uint32_t o = (uint32_t)(row * 64 + c16 * 16);
            CP16(base + term * A_TERM_BYTES + SW(o),
                 Wspl + (size_t)term * termstride + (size_t)(tm + row) * Ci + k0 + c16 * 8);
        }
#pragma unroll
        for (int i = 0; i < 4; ++i) {
            int idx = i * 128 + tid;
            int ridx = idx >> 2, c16 = idx & 3;
            uint32_t o = (uint32_t)(ridx * 64 + c16 * 16);
            CP16(base + A_BYTES + SW(o),
                 Bt + (size_t)(tn + ridx) * Ci + k0 + c16 * 8);
        }
        CP_COMMIT();
    };

    GEMM_MAINLOOP();

#pragma unroll
    for (int mi = 0; mi < 4; ++mi) {
#pragma unroll
        for (int h = 0; h < 2; ++h) {
            int co = tm + wm * 64 + mi * 16 + h * 8 + (lane >> 2);
            float scv = scale ? scale[co] : 1.f;
            float shv = shift ? shift[co] : 0.f;
            float* op = out + ((size_t)b * Co + co) * LLv + tn;
            const float* rp = resid ? resid + ((size_t)b * Co + co) * LLv + tn : nullptr;
#pragma unroll
            for (int nj = 0; nj < 8; ++nj) {
                int col = wn * 64 + nj * 8 + (lane & 3) * 2;
                float2 o;
                o.x = acc[mi][nj][h * 2 + 0] * scv + shv;
                o.y = acc[mi][nj][h * 2 + 1] * scv + shv;
                if (rp) {
                    float2 rv = *(const float2*)(rp + col);
                    o.x += rv.x; o.y += rv.y;
                }
                *(float2*)(op + col) = o;
            }
        }
    }
}

// -------------------- M partials = k^T v over L-slices ----------------------
__global__ void __launch_bounds__(256) kv_outer_k(
    const float* __restrict__ skv, float* __restrict__ Mp) {
    int bh = blockIdx.x;
    int spl = blockIdx.y;
    int b = bh >> 3, h = bh & 7;
    const float* K = skv + ((size_t)b * CQKV + 512 + h * HD) * LLv;
    const float* V = skv + ((size_t)b * CQKV + 1024 + h * HD) * LLv;
    __shared__ float Ks[64][65];
    __shared__ float Vs[64][65];
    float acc[4][4];
#pragma unroll
    for (int i = 0; i < 4; ++i)
#pragma unroll
        for (int j = 0; j < 4; ++j) acc[i][j] = 0.f;
    int tr = threadIdx.x >> 4, tc = threadIdx.x & 15;
    int row = threadIdx.x >> 2, cb = (threadIdx.x & 3) * 16;
    int lbeg = spl * (LLv / KVSPL);
    for (int l0 = lbeg; l0 < lbeg + LLv / KVSPL; l0 += 64) {
        __syncthreads();
#pragma unroll
        for (int u = 0; u < 16; u += 4) {
            float4 kv = *(const float4*)&K[(size_t)row * LLv + l0 + cb + u];
            Ks[row][cb + u] = kv.x; Ks[row][cb + u + 1] = kv.y;
            Ks[row][cb + u + 2] = kv.z; Ks[row][cb + u + 3] = kv.w;
            float4 vv = *(const float4*)&V[(size_t)row * LLv + l0 + cb + u];
            Vs[row][cb + u] = vv.x; Vs[row][cb + u + 1] = vv.y;
            Vs[row][cb + u + 2] = vv.z; Vs[row][cb + u + 3] = vv.w;
        }
        __syncthreads();
#pragma unroll
        for (int ll = 0; ll < 64; ++ll) {
            float a[4], c[4];
#pragma unroll
            for (int i = 0; i < 4; ++i) a[i] = Ks[tr * 4 + i][ll];
#pragma unroll
            for (int i = 0; i < 4; ++i) c[i] = Vs[tc * 4 + i][ll];
#pragma unroll
            for (int i = 0; i < 4; ++i)
#pragma unroll
                for (int j = 0; j < 4; ++j) acc[i][j] += a[i] * c[j];
        }
    }
    float* Mo = Mp + ((size_t)spl * 32 + bh) * (HD * HD);
#pragma unroll
    for (int i = 0; i < 4; ++i)
#pragma unroll
        for (int j = 0; j < 4; ++j)
            Mo[(tr * 4 + i) * HD + tc * 4 + j] = acc[i][j];
}

// -------------------- o = q @ (sum Mp) -> spike -> soT fp16 -----------------
__global__ void __launch_bounds__(256) qm_spike_k(
    const float* __restrict__ skv, const float* __restrict__ Mp, __half* __restrict__ soT) {
    int bh = blockIdx.y;
    int b = bh >> 3, h = bh & 7;
    int l = blockIdx.x * 256 + threadIdx.x;
    __shared__ float Ms[HD * HD];
#pragma unroll
    for (int u = 0; u < 16; ++u) {
        int idx = u * 256 + threadIdx.x;
        float s = 0.f;
#pragma unroll
        for (int sp = 0; sp < KVSPL; ++sp)
            s += Mp[((size_t)sp * 32 + bh) * (HD * HD) + idx];
        Ms[idx] = s;
    }
    __syncthreads();
    const float* Q = skv + ((size_t)b * CQKV + h * HD) * LLv + l;
    float acc[HD];
#pragma unroll
    for (int jp = 0; jp < HD; ++jp) acc[jp] = 0.f;
    for (int j = 0; j < HD; ++j) {
        float qv = Q[(size_t)j * LLv];
#pragma unroll
        for (int jp = 0; jp < HD; ++jp) acc[jp] += qv * Ms[j * HD + jp];
    }
    __half* O = soT + ((size_t)b * LLv + l) * CC + h * HD;
#pragma unroll
    for (int jp = 0; jp < HD; ++jp) {
        float o = acc[jp] * 0.125f;
        O[jp] = __float2half_rn(((o / 1.5f - 1.f) >= 0.f) ? 1.f : 0.f);
    }
}

// ---------------------------------------------------------------------------
extern "C" void kernel_launch(void* const* d_in, const int* in_sizes, int n_in,
                              void* d_out, int out_size) {
    const float* x       = (const float*)d_in[0];
    const float* attn_bn = (const float*)d_in[1];
    const float* q_w     = (const float*)d_in[2];
    const float* q_bn    = (const float*)d_in[3];
    const float* k_w     = (const float*)d_in[4];
    const float* k_bn    = (const float*)d_in[5];
    const float* v_w     = (const float*)d_in[6];
    const float* v_bn    = (const float*)d_in[7];
    const float* proj_w  = (const float*)d_in[8];
    const float* proj_b  = (const float*)d_in[9];
    const float* mlp_bn  = (const float*)d_in[10];
    const float* fc1_w   = (const float*)d_in[11];
    const float* fc1_b   = (const float*)d_in[12];
    const float* fc1_bn  = (const float*)d_in[13];
    const float* fc2_w   = (const float*)d_in[14];
    const float* fc2_b   = (const float*)d_in[15];
    float* out = (float*)d_out;

    float *skv, *x1, *Mp, *scale, *shift;
    __half *xqT, *soT, *s2T, *w;
    cudaGetSymbolAddress((void**)&skv, g_skv);
    cudaGetSymbolAddress((void**)&x1,  g_x1);
    cudaGetSymbolAddress((void**)&Mp,  g_Mp);
    cudaGetSymbolAddress((void**)&scale, g_scale);
    cudaGetSymbolAddress((void**)&shift, g_shift);
    cudaGetSymbolAddress((void**)&xqT, g_xqT);
    cudaGetSymbolAddress((void**)&soT, g_soT);
    cudaGetSymbolAddress((void**)&s2T, g_s2T);
    cudaGetSymbolAddress((void**)&w,   g_w);

    cudaFuncSetAttribute(gemm_mma_k, cudaFuncAttributeMaxDynamicSharedMemorySize, DYN_SMEM);
    cudaFuncSetAttribute(gemm_qkv_k, cudaFuncAttributeMaxDynamicSharedMemorySize, DYN_SMEM);
    cudaFuncSetAttribute(gemm_fc1_k, cudaFuncAttributeMaxDynamicSharedMemorySize, DYN_SMEM);

    __half* wqkv = w;                       // [2][1536][512]
    __half* wp   = w + 6 * (size_t)SZ;      // [2][512][512]
    __half* wf1  = w + 8 * (size_t)SZ;      // [2][2048][512]
    __half* wf2  = wf1 + 2 * (size_t)SZH;   // [2][512][2048]

    bnprep_all<<<dim3(8, 6), 256>>>(attn_bn, q_bn, k_bn, v_bn, mlp_bn, fc1_bn, fc1_b,
                                    scale, shift);
    wsplit_all<<<(4 * SZ + 2 * SZH) / 256, 256>>>(q_w, k_w, v_w, proj_w, fc1_w, fc2_w,
                                                  wqkv, wp, wf1, wf2);

    dim3 ltr(32, 8);
    dim3 gtr512(16, 16, BB);

    // attn input spikes (BN_attn + LIF) -> xqT fp16 [B,L,C]
    lif_tr_k<<<gtr512, ltr>>>(x, xqT, scale, shift, CC);

    // fused q/k/v GEMM + BN + LIF -> skv spikes fp32 [B,1536,L]
    gemm_qkv_k<<<dim3(16, 12, 4), 128, DYN_SMEM>>>(wqkv, xqT, skv,
                                                   scale + 2048, shift + 2048);

    // attention: exact q (k^T v) with split-L partials
    kv_outer_k<<<dim3(32, KVSPL), 256>>>(skv, Mp);
    qm_spike_k<<<dim3(8, 32), 256>>>(skv, Mp, soT);

    // proj + residual -> x1
    gemm_mma_k<<<dim3(16, 4, 4), 128, DYN_SMEM>>>(wp, soT, x1, nullptr, proj_b, x, CC, CC);

    // MLP: BN+LIF -> xqT, fc1 fused -> s2T fp16, fc2 + residual
    lif_tr_k<<<gtr512, ltr>>>(x1, xqT, scale + 4 * 2048, shift + 4 * 2048, CC);
    gemm_fc1_k<<<dim3(16, 16, 4), 128, DYN_SMEM>>>(wf1, xqT, s2T,
                                                   scale + 5 * 2048, shift + 5 * 2048);
    gemm_mma_k<<<dim3(16, 4, 4), 128, DYN_SMEM>>>(wf2, s2T, out, nullptr, fc2_b, x1, CC, HIDN);
}